// round 6
// baseline (speedup 1.0000x reference)
#include <cuda_runtime.h>
#include <cuda_bf16.h>
#include <cstdint>
#include <cstddef>

// ---------------------------------------------------------------------------
// TTLinear. Phase A: 3 big GEMMs (tf32 tensor cores). Phase B: one persistent
// kernel, 128 sequential SGD steps, 8 grid barriers/step, double-buffered
// fp32 tiles with half-block pairing (two 64x64 units per 512-thread block).
// ---------------------------------------------------------------------------

constexpr int T_  = 128;
constexpr int NB  = 256;
constexpr int DD  = 1024;
constexpr int HH  = 1024;
constexpr int H4  = 256;
constexpr int NH  = NB * HH;    // 262144
constexpr int MN  = NB * H4;    // 65536
constexpr float LR = 1e-3f;
constexpr float C2 = 2.0f / (float)(NB * HH);

constexpr int SL   = 68;        // padded smem row (floats)
constexpr int SLAB = 16 * SL;   // one k-slab buffer

// ------------------------- device scratch ----------------------------------
__device__ float g_Z[(size_t)T_ * NH];
__device__ float g_Y[(size_t)T_ * NH];
__device__ float g_Q[(size_t)T_ * NH];
__device__ float g_W1[H4 * HH];
__device__ float g_b1[H4];
__device__ float g_W2[HH * H4];
__device__ float g_b2[HH];
__device__ float g_a[MN];
__device__ float g_h[MN];
__device__ float g_h2[MN];
__device__ float g_da[MN];
__device__ float g_dr[NB * HH];
__device__ float g_part[8 * MN];

__device__ unsigned g_cnt = 0;
__device__ unsigned g_gen = 0;

// ------------------------------ helpers ------------------------------------
__device__ __forceinline__ float gelu_f(float x) {
    return 0.5f * x * (1.0f + erff(x * 0.70710678118654752f));
}
__device__ __forceinline__ float gelu_grad(float x) {
    float cdf = 0.5f * (1.0f + erff(x * 0.70710678118654752f));
    float pdf = 0.3989422804014327f * expf(-0.5f * x * x);
    return cdf + x * pdf;
}
__device__ __forceinline__ float to_tf32(float x) {
    uint32_t u;
    asm("cvt.rna.tf32.f32 %0, %1;" : "=r"(u) : "f"(x));
    return __uint_as_float(u);
}
__device__ __forceinline__ void mma_tf32(float (&c)[4], const uint32_t (&a)[4],
                                         const uint32_t (&b)[2]) {
    asm volatile(
        "mma.sync.aligned.m16n8k8.row.col.f32.tf32.tf32.f32 "
        "{%0,%1,%2,%3}, {%4,%5,%6,%7}, {%8,%9}, {%0,%1,%2,%3};"
        : "+f"(c[0]), "+f"(c[1]), "+f"(c[2]), "+f"(c[3])
        : "r"(a[0]), "r"(a[1]), "r"(a[2]), "r"(a[3]), "r"(b[0]), "r"(b[1]));
}

// Bounded grid barrier (degrades to wrong output, never hangs the container).
__device__ __forceinline__ void grid_sync(unsigned nb) {
    __syncthreads();
    if (threadIdx.x == 0) {
        unsigned gen = *(volatile unsigned*)&g_gen;
        __threadfence();
        if (atomicAdd(&g_cnt, 1) == nb - 1) {
            g_cnt = 0;
            __threadfence();
            atomicAdd(&g_gen, 1);
        } else {
            for (int spin = 0; spin < 1000000; spin++) {
                if (*(volatile unsigned*)&g_gen != gen) break;
                __nanosleep(32);
            }
        }
        __threadfence();
    }
    __syncthreads();
}

// ---------------------------------------------------------------------------
// Phase A: C[M,N] = A[M,K] @ B[N,K]^T via tf32 mma.sync. 128x128 block tile,
// 256 threads = 8 warps (2x4), warp tile 64x32, double-buffered smem.
// ---------------------------------------------------------------------------
__global__ __launch_bounds__(256, 2) void gemm_nt_tf32(
    const float* __restrict__ A, const float* __restrict__ B,
    float* __restrict__ C, int M, int N, int K)
{
    __shared__ float As[2][16][136];
    __shared__ float Bs[2][16][136];
    const int m0 = blockIdx.x * 128, n0 = blockIdx.y * 128;
    const int tid = threadIdx.x;
    const int lrow = tid & 127, lc8 = (tid >> 7) * 8;
    const int w = tid >> 5, lane = tid & 31;
    const int wm = w >> 2, wn = w & 3;
    const int g = lane >> 2, q = lane & 3;

    float acc[4][4][4] = {};

    const float* Ag = A + (size_t)(m0 + lrow) * K + lc8;
    const float* Bg = B + (size_t)(n0 + lrow) * K + lc8;

    float4 ra0 = *(const float4*)(Ag);
    float4 ra1 = *(const float4*)(Ag + 4);
    float4 rb0 = *(const float4*)(Bg);
    float4 rb1 = *(const float4*)(Bg + 4);

    const int S = K / 16;
    for (int s = 0; s < S; s++) {
        const int buf = s & 1;
        {   // store current regs -> smem (tf32-rounded)
            float* pa = &As[buf][lc8][lrow];
            pa[0*136] = to_tf32(ra0.x); pa[1*136] = to_tf32(ra0.y);
            pa[2*136] = to_tf32(ra0.z); pa[3*136] = to_tf32(ra0.w);
            pa[4*136] = to_tf32(ra1.x); pa[5*136] = to_tf32(ra1.y);
            pa[6*136] = to_tf32(ra1.z); pa[7*136] = to_tf32(ra1.w);
            float* pb = &Bs[buf][lc8][lrow];
            pb[0*136] = to_tf32(rb0.x); pb[1*136] = to_tf32(rb0.y);
            pb[2*136] = to_tf32(rb0.z); pb[3*136] = to_tf32(rb0.w);
            pb[4*136] = to_tf32(rb1.x); pb[5*136] = to_tf32(rb1.y);
            pb[6*136] = to_tf32(rb1.z); pb[7*136] = to_tf32(rb1.w);
        }
        if (s + 1 < S) {   // prefetch next slab
            const float* a2 = Ag + (s + 1) * 16;
            const float* b2 = Bg + (s + 1) * 16;
            ra0 = *(const float4*)(a2);     ra1 = *(const float4*)(a2 + 4);
            rb0 = *(const float4*)(b2);     rb1 = *(const float4*)(b2 + 4);
        }
        __syncthreads();
#pragma unroll
        for (int kc = 0; kc < 16; kc += 8) {
            uint32_t af[4][4], bf[4][2];
#pragma unroll
            for (int mt = 0; mt < 4; mt++) {
                int r = wm * 64 + mt * 16 + g;
                af[mt][0] = __float_as_uint(As[buf][kc + q][r]);
                af[mt][1] = __float_as_uint(As[buf][kc + q][r + 8]);
                af[mt][2] = __float_as_uint(As[buf][kc + q + 4][r]);
                af[mt][3] = __float_as_uint(As[buf][kc + q + 4][r + 8]);
            }
#pragma unroll
            for (int nt = 0; nt < 4; nt++) {
                int c = wn * 32 + nt * 8 + g;
                bf[nt][0] = __float_as_uint(Bs[buf][kc + q][c]);
                bf[nt][1] = __float_as_uint(Bs[buf][kc + q + 4][c]);
            }
#pragma unroll
            for (int mt = 0; mt < 4; mt++)
#pragma unroll
                for (int nt = 0; nt < 4; nt++)
                    mma_tf32(acc[mt][nt], af[mt], bf[nt]);
        }
        __syncthreads();
    }
#pragma unroll
    for (int mt = 0; mt < 4; mt++)
#pragma unroll
        for (int nt = 0; nt < 4; nt++) {
            int r = m0 + wm * 64 + mt * 16 + g;
            int c = n0 + wn * 32 + nt * 8 + q * 2;
            *(float2*)&C[(size_t)r * N + c] =
                make_float2(acc[mt][nt][0], acc[mt][nt][1]);
            *(float2*)&C[(size_t)(r + 8) * N + c] =
                make_float2(acc[mt][nt][2], acc[mt][nt][3]);
        }
}

// ---------------------------------------------------------------------------
// Phase B tile primitive: 64x64 tile, 256 threads (one half-block), 4x4
// microtile, double-buffered smem, ONE __syncthreads per 16-k slab.
// MODE 0 NT: A[m,k],B[n,k]; MODE 1 NN: A[m,k],B[k,n]; MODE 2 TN: A[k,m],B[k,n]
// ---------------------------------------------------------------------------
template <int MODE>
__device__ __forceinline__ void tile_db(
    const float* __restrict__ A, const float* __restrict__ B, float* hsm,
    int lda, int ldb, int m0, int n0, int kbeg, int kend, int htid,
    float (&acc)[4][4])
{
    float* smA = hsm;
    float* smB = hsm + 2 * SLAB;
    const int rowm = htid >> 2,  c4m = (htid & 3) * 4;
    const int krow = htid >> 4,  c4k = (htid & 15) * 4;
    const int tx = htid & 15,    ty = htid >> 4;
    const int nslab = (kend - kbeg) >> 4;
    float4 ra, rb;

    {   // fetch slab 0
        int k0 = kbeg;
        ra = (MODE == 2) ? *(const float4*)(A + (size_t)(k0 + krow) * lda + m0 + c4k)
                         : *(const float4*)(A + (size_t)(m0 + rowm) * lda + k0 + c4m);
        rb = (MODE == 0) ? *(const float4*)(B + (size_t)(n0 + rowm) * ldb + k0 + c4m)
                         : *(const float4*)(B + (size_t)(k0 + krow) * ldb + n0 + c4k);
    }
    for (int s = 0; s < nslab; s++) {
        const int buf = s & 1;
        {   // store current regs
            float* dA = smA + buf * SLAB;
            float* dB = smB + buf * SLAB;
            if (MODE == 2) { *(float4*)(dA + krow * SL + c4k) = ra; }
            else {
                dA[(c4m + 0) * SL + rowm] = ra.x; dA[(c4m + 1) * SL + rowm] = ra.y;
                dA[(c4m + 2) * SL + rowm] = ra.z; dA[(c4m + 3) * SL + rowm] = ra.w;
            }
            if (MODE == 0) {
                dB[(c4m + 0) * SL + rowm] = rb.x; dB[(c4m + 1) * SL + rowm] = rb.y;
                dB[(c4m + 2) * SL + rowm] = rb.z; dB[(c4m + 3) * SL + rowm] = rb.w;
            } else { *(float4*)(dB + krow * SL + c4k) = rb; }
        }
        if (s + 1 < nslab) {   // prefetch next slab
            int k0 = kbeg + (s + 1) * 16;
            ra = (MODE == 2) ? *(const float4*)(A + (size_t)(k0 + krow) * lda + m0 + c4k)
                             : *(const float4*)(A + (size_t)(m0 + rowm) * lda + k0 + c4m);
            rb = (MODE == 0) ? *(const float4*)(B + (size_t)(n0 + rowm) * ldb + k0 + c4m)
                             : *(const float4*)(B + (size_t)(k0 + krow) * ldb + n0 + c4k);
        }
        __syncthreads();
        const float* cA = smA + buf * SLAB;
        const float* cB = smB + buf * SLAB;
#pragma unroll
        for (int k = 0; k < 16; k++) {
            float4 a = *(const float4*)(cA + k * SL + ty * 4);
            float4 b = *(const float4*)(cB + k * SL + tx * 4);
            float av[4] = {a.x, a.y, a.z, a.w};
            float bv[4] = {b.x, b.y, b.z, b.w};
#pragma unroll
            for (int i = 0; i < 4; i++)
#pragma unroll
                for (int j = 0; j < 4; j++) acc[i][j] += av[i] * bv[j];
        }
        __syncthreads();
    }
}

// ---------------------------------------------------------------------------
// Persistent Phase B kernel: 512 threads, two 64x64 tile-units per block
// (halves run in lockstep; all per-region unit counts are even).
// ---------------------------------------------------------------------------
__global__ __launch_bounds__(512, 1) void ttt_persistent(float* __restrict__ out,
                                                         int nb)
{
    __shared__ __align__(16) float PB[2][4 * SLAB];
    const int bid = blockIdx.x, tid = threadIdx.x;
    const int half = tid >> 8, htid = tid & 255;
    const int tx = htid & 15, ty = htid >> 4;
    float* hsm = PB[half];
    const int ustride = nb * 2;
    const int ubase = bid * 2 + half;
    const int gw = (bid * 512 + tid) >> 5, lane = tid & 31;

    for (int step = 0; step <= T_; step++) {
        // ---- R0a: S10 of step-1: out[t-1] = Qt + h2@W2^T + b2 (64 units) ----
        if (step > 0) {
            const int t = step - 1;
            const float* Qt = g_Q + (size_t)t * NH;
            float* od = out + (size_t)t * NH;
            for (int u = ubase; u < 64; u += ustride) {
                int m0 = (u & 3) * 64, n0 = (u >> 2) * 64;
                float acc[4][4] = {};
                tile_db<0>(g_h2, g_W2, hsm, H4, H4, m0, n0, 0, H4, htid, acc);
                int n = n0 + tx * 4;
                float4 bb = *(const float4*)(g_b2 + n);
#pragma unroll
                for (int r = 0; r < 4; r++) {
                    int m = m0 + ty * 4 + r;
                    float4 qv = *(const float4*)(Qt + (size_t)m * HH + n);
                    *(float4*)(od + (size_t)m * HH + n) = make_float4(
                        qv.x + acc[r][0] + bb.x, qv.y + acc[r][1] + bb.y,
                        qv.z + acc[r][2] + bb.z, qv.w + acc[r][3] + bb.w);
                }
            }
        }
        // ---- R0b: S1 split-K partials: Zt @ W1^T (128 units) ----
        if (step < T_) {
            const float* Zt = g_Z + (size_t)step * NH;
            for (int u = ubase; u < 128; u += ustride) {
                int sk = u & 7, tile = u >> 3;
                int m0 = (tile & 3) * 64, n0 = (tile >> 2) * 64;
                float acc[4][4] = {};
                tile_db<0>(Zt, g_W1, hsm, DD, DD, m0, n0, sk * 128, sk * 128 + 128,
                           htid, acc);
                float* cp = g_part + (size_t)sk * MN;
#pragma unroll
                for (int r = 0; r < 4; r++)
                    *(float4*)(cp + (size_t)(m0 + ty * 4 + r) * H4 + n0 + tx * 4) =
                        make_float4(acc[r][0], acc[r][1], acc[r][2], acc[r][3]);
            }
        }
        grid_sync(nb);
        if (step == T_) break;

        const int t = step;
        const float* Zt = g_Z + (size_t)t * NH;
        const float* Yt = g_Y + (size_t)t * NH;
        const float* Qt = g_Q + (size_t)t * NH;

        // ---- R1: a = sum(part)+b1; h = gelu(a) ----
        for (int idx = bid * 512 + tid; idx < MN; idx += nb * 512) {
            float s = 0.f;
#pragma unroll
            for (int z = 0; z < 8; z++) s += g_part[(size_t)z * MN + idx];
            s += g_b1[idx & (H4 - 1)];
            g_a[idx] = s;
            g_h[idx] = gelu_f(s);
        }
        grid_sync(nb);

        // ---- R2: dr = C2*(Zt + h@W2^T + b2 - Yt) (64 units, OLD W2) ----
        for (int u = ubase; u < 64; u += ustride) {
            int m0 = (u & 3) * 64, n0 = (u >> 2) * 64;
            float acc[4][4] = {};
            tile_db<0>(g_h, g_W2, hsm, H4, H4, m0, n0, 0, H4, htid, acc);
            int n = n0 + tx * 4;
            float4 bb = *(const float4*)(g_b2 + n);
#pragma unroll
            for (int r = 0; r < 4; r++) {
                int m = m0 + ty * 4 + r;
                float4 zz = *(const float4*)(Zt + (size_t)m * HH + n);
                float4 yy = *(const float4*)(Yt + (size_t)m * HH + n);
                *(float4*)(g_dr + (size_t)m * HH + n) = make_float4(
                    C2 * (zz.x + acc[r][0] + bb.x - yy.x),
                    C2 * (zz.y + acc[r][1] + bb.y - yy.y),
                    C2 * (zz.z + acc[r][2] + bb.z - yy.z),
                    C2 * (zz.w + acc[r][3] + bb.w - yy.w));
            }
        }
        grid_sync(nb);

        // ---- R3: da_pre partials = dr @ W2 (NN, 128 units, OLD W2) ----
        for (int u = ubase; u < 128; u += ustride) {
            int sk = u & 7, tile = u >> 3;
            int m0 = (tile & 3) * 64, n0 = (tile >> 2) * 64;
            float acc[4][4] = {};
            tile_db<1>(g_dr, g_W2, hsm, HH, H4, m0, n0, sk * 128, sk * 128 + 128,
                       htid, acc);
            float* cp = g_part + (size_t)sk * MN;
#pragma unroll
            for (int r = 0; r < 4; r++)
                *(float4*)(cp + (size_t)(m0 + ty * 4 + r) * H4 + n0 + tx * 4) =
                    make_float4(acc[r][0], acc[r][1], acc[r][2], acc[r][3]);
        }
        grid_sync(nb);

        // ---- R4: da = sum(part) * gelu'(a) ----
        for (int idx = bid * 512 + tid; idx < MN; idx += nb * 512) {
            float s = 0.f;
#pragma unroll
            for (int z = 0; z < 8; z++) s += g_part[(size_t)z * MN + idx];
            g_da[idx] = s * gelu_grad(g_a[idx]);
        }
        grid_sync(nb);

        // ---- R5: W2/W1 updates (128 TN units, Kn=256) + bias colsums ----
        for (int u = ubase; u < 128; u += ustride) {
            if (u < 64) {
                int i0 = (u & 15) * 64, j0 = (u >> 4) * 64;
                float acc[4][4] = {};
                tile_db<2>(g_dr, g_h, hsm, HH, H4, i0, j0, 0, NB, htid, acc);
#pragma unroll
                for (int r = 0; r < 4; r++) {
                    float* pp = g_W2 + (size_t)(i0 + ty * 4 + r) * H4 + j0 + tx * 4;
                    float4 o = *(float4*)pp;
                    o.x -= LR * acc[r][0]; o.y -= LR * acc[r][1];
                    o.z -= LR * acc[r][2]; o.w -= LR * acc[r][3];
                    *(float4*)pp = o;
                }
            } else {
                int v = u - 64;
                int j0 = (v & 3) * 64, i0 = (v >> 2) * 64;
                float acc[4][4] = {};
                tile_db<2>(g_da, Zt, hsm, H4, DD, j0, i0, 0, NB, htid, acc);
#pragma unroll
                for (int r = 0; r < 4; r++) {
                    float* pp = g_W1 + (size_t)(j0 + ty * 4 + r) * DD + i0 + tx * 4;
                    float4 o = *(float4*)pp;
                    o.x -= LR * acc[r][0]; o.y -= LR * acc[r][1];
                    o.z -= LR * acc[r][2]; o.w -= LR * acc[r][3];
                    *(float4*)pp = o;
                }
            }
        }
        // bias updates: warp-parallel column sums (no syncs -> safe divergence)
        for (int c = gw; c < HH; c += nb * 16) {
            float s = 0.f;
            for (int n = lane; n < NB; n += 32) s += g_dr[(size_t)n * HH + c];
#pragma unroll
            for (int o = 16; o > 0; o >>= 1) s += __shfl_xor_sync(0xffffffffu, s, o);
            if (lane == 0) g_b2[c] -= LR * s;
        }
        for (int c = gw; c < H4; c += nb * 16) {
            float s = 0.f;
            for (int n = lane; n < NB; n += 32) s += g_da[(size_t)n * H4 + c];
#pragma unroll
            for (int o = 16; o > 0; o >>= 1) s += __shfl_xor_sync(0xffffffffu, s, o);
            if (lane == 0) g_b1[c] -= LR * s;
        }
        grid_sync(nb);

        // ---- R6: a2 partials = Qt @ W1_new^T (128 units) ----
        for (int u = ubase; u < 128; u += ustride) {
            int sk = u & 7, tile = u >> 3;
            int m0 = (tile & 3) * 64, n0 = (tile >> 2) * 64;
            float acc[4][4] = {};
            tile_db<0>(Qt, g_W1, hsm, DD, DD, m0, n0, sk * 128, sk * 128 + 128,
                       htid, acc);
            float* cp = g_part + (size_t)sk * MN;
#pragma unroll
            for (int r = 0; r < 4; r++)
                *(float4*)(cp + (size_t)(m0 + ty * 4 + r) * H4 + n0 + tx * 4) =
                    make_float4(acc[r][0], acc[r][1], acc[r][2], acc[r][3]);
        }
        grid_sync(nb);

        // ---- R7: h2 = gelu(sum(part) + b1_new) ----
        for (int idx = bid * 512 + tid; idx < MN; idx += nb * 512) {
            float s = 0.f;
#pragma unroll
            for (int z = 0; z < 8; z++) s += g_part[(size_t)z * MN + idx];
            s += g_b1[idx & (H4 - 1)];
            g_h2[idx] = gelu_f(s);
        }
        grid_sync(nb);
    }
}

// ---------------------------------------------------------------------------
// kernel_launch
// ---------------------------------------------------------------------------
extern "C" void kernel_launch(void* const* d_in, const int* in_sizes, int n_in,
                              void* d_out, int out_size)
{
    (void)in_sizes; (void)n_in; (void)out_size;
    const float* in_seq = (const float*)d_in[0];
    const float* t_k = (const float*)d_in[1];
    const float* t_v = (const float*)d_in[2];
    const float* t_q = (const float*)d_in[3];

    float *Z, *Y, *Q, *W1, *b1, *W2, *b2;
    cudaGetSymbolAddress((void**)&Z, g_Z);
    cudaGetSymbolAddress((void**)&Y, g_Y);
    cudaGetSymbolAddress((void**)&Q, g_Q);
    cudaGetSymbolAddress((void**)&W1, g_W1);
    cudaGetSymbolAddress((void**)&b1, g_b1);
    cudaGetSymbolAddress((void**)&W2, g_W2);
    cudaGetSymbolAddress((void**)&b2, g_b2);

    cudaMemcpyAsync(W1, d_in[4], sizeof(float) * H4 * HH, cudaMemcpyDeviceToDevice, 0);
    cudaMemcpyAsync(b1, d_in[5], sizeof(float) * H4, cudaMemcpyDeviceToDevice, 0);
    cudaMemcpyAsync(W2, d_in[6], sizeof(float) * HH * H4, cudaMemcpyDeviceToDevice, 0);
    cudaMemcpyAsync(b2, d_in[7], sizeof(float) * HH, cudaMemcpyDeviceToDevice, 0);

    // Phase A: tf32 tensor-core GEMMs
    const int M_big = T_ * NB;
    dim3 gA(M_big / 128, HH / 128);
    gemm_nt_tf32<<<gA, 256>>>(in_seq, t_k, Z, M_big, HH, DD);
    gemm_nt_tf32<<<gA, 256>>>(in_seq, t_v, Y, M_big, HH, DD);
    gemm_nt_tf32<<<gA, 256>>>(in_seq, t_q, Q, M_big, HH, DD);

    // Phase B: one persistent kernel, exactly one block per SM.
    int sms = 0;
    cudaDeviceGetAttribute(&sms, cudaDevAttrMultiProcessorCount, 0);
    if (sms <= 0 || sms > 148) sms = 148;
    ttt_persistent<<<sms, 512>>>((float*)d_out, sms);
}

// round 7
// speedup vs baseline: 1.0009x; 1.0009x over previous
#include <cuda_runtime.h>
#include <cuda_bf16.h>
#include <cstdint>
#include <cstddef>

// ---------------------------------------------------------------------------
// TTLinear. Phase A: 3 big GEMMs (tf32 tensor cores). Phase B: one persistent
// kernel, 128 sequential SGD steps, 8 grid barriers/step, double-buffered
// fp32 tiles with half-block pairing (two 64x64 units per 512-thread block).
// R7 change: grid barrier is a HOT SPIN (no __nanosleep) — the nanosleep
// wakeup quantum (~17us/barrier x 1024 barriers) dominated all prior rounds.
// ---------------------------------------------------------------------------

constexpr int T_  = 128;
constexpr int NB  = 256;
constexpr int DD  = 1024;
constexpr int HH  = 1024;
constexpr int H4  = 256;
constexpr int NH  = NB * HH;    // 262144
constexpr int MN  = NB * H4;    // 65536
constexpr float LR = 1e-3f;
constexpr float C2 = 2.0f / (float)(NB * HH);

constexpr int SL   = 68;        // padded smem row (floats)
constexpr int SLAB = 16 * SL;   // one k-slab buffer

// ------------------------- device scratch ----------------------------------
__device__ float g_Z[(size_t)T_ * NH];
__device__ float g_Y[(size_t)T_ * NH];
__device__ float g_Q[(size_t)T_ * NH];
__device__ float g_W1[H4 * HH];
__device__ float g_b1[H4];
__device__ float g_W2[HH * H4];
__device__ float g_b2[HH];
__device__ float g_a[MN];
__device__ float g_h[MN];
__device__ float g_h2[MN];
__device__ float g_da[MN];
__device__ float g_dr[NB * HH];
__device__ float g_part[8 * MN];

__device__ unsigned g_cnt = 0;
__device__ unsigned g_gen = 0;

// ------------------------------ helpers ------------------------------------
__device__ __forceinline__ float gelu_f(float x) {
    return 0.5f * x * (1.0f + erff(x * 0.70710678118654752f));
}
__device__ __forceinline__ float gelu_grad(float x) {
    float cdf = 0.5f * (1.0f + erff(x * 0.70710678118654752f));
    float pdf = 0.3989422804014327f * expf(-0.5f * x * x);
    return cdf + x * pdf;
}
__device__ __forceinline__ float to_tf32(float x) {
    uint32_t u;
    asm("cvt.rna.tf32.f32 %0, %1;" : "=r"(u) : "f"(x));
    return __uint_as_float(u);
}
__device__ __forceinline__ void mma_tf32(float (&c)[4], const uint32_t (&a)[4],
                                         const uint32_t (&b)[2]) {
    asm volatile(
        "mma.sync.aligned.m16n8k8.row.col.f32.tf32.tf32.f32 "
        "{%0,%1,%2,%3}, {%4,%5,%6,%7}, {%8,%9}, {%0,%1,%2,%3};"
        : "+f"(c[0]), "+f"(c[1]), "+f"(c[2]), "+f"(c[3])
        : "r"(a[0]), "r"(a[1]), "r"(a[2]), "r"(a[3]), "r"(b[0]), "r"(b[1]));
}

// HOT-SPIN grid barrier. No __nanosleep: its multi-us wakeup quantum cost
// ~17us per barrier. Pure volatile L2 polling detects release in ~1 L2 RTT.
// Bounded (1M polls ~0.1s) so a sync bug produces wrong output, not a hang.
__device__ __forceinline__ void grid_sync(unsigned nb) {
    __syncthreads();
    if (threadIdx.x == 0) {
        unsigned gen = *(volatile unsigned*)&g_gen;
        __threadfence();
        if (atomicAdd(&g_cnt, 1) == nb - 1) {
            g_cnt = 0;
            __threadfence();
            atomicAdd(&g_gen, 1);
        } else {
            for (int spin = 0; spin < 1000000; spin++) {
                if (*(volatile unsigned*)&g_gen != gen) break;
            }
        }
        __threadfence();
    }
    __syncthreads();
}

// ---------------------------------------------------------------------------
// Phase A: C[M,N] = A[M,K] @ B[N,K]^T via tf32 mma.sync. 128x128 block tile,
// 256 threads = 8 warps (2x4), warp tile 64x32, double-buffered smem.
// ---------------------------------------------------------------------------
__global__ __launch_bounds__(256, 2) void gemm_nt_tf32(
    const float* __restrict__ A, const float* __restrict__ B,
    float* __restrict__ C, int M, int N, int K)
{
    __shared__ float As[2][16][136];
    __shared__ float Bs[2][16][136];
    const int m0 = blockIdx.x * 128, n0 = blockIdx.y * 128;
    const int tid = threadIdx.x;
    const int lrow = tid & 127, lc8 = (tid >> 7) * 8;
    const int w = tid >> 5, lane = tid & 31;
    const int wm = w >> 2, wn = w & 3;
    const int g = lane >> 2, q = lane & 3;

    float acc[4][4][4] = {};

    const float* Ag = A + (size_t)(m0 + lrow) * K + lc8;
    const float* Bg = B + (size_t)(n0 + lrow) * K + lc8;

    float4 ra0 = *(const float4*)(Ag);
    float4 ra1 = *(const float4*)(Ag + 4);
    float4 rb0 = *(const float4*)(Bg);
    float4 rb1 = *(const float4*)(Bg + 4);

    const int S = K / 16;
    for (int s = 0; s < S; s++) {
        const int buf = s & 1;
        {
            float* pa = &As[buf][lc8][lrow];
            pa[0*136] = to_tf32(ra0.x); pa[1*136] = to_tf32(ra0.y);
            pa[2*136] = to_tf32(ra0.z); pa[3*136] = to_tf32(ra0.w);
            pa[4*136] = to_tf32(ra1.x); pa[5*136] = to_tf32(ra1.y);
            pa[6*136] = to_tf32(ra1.z); pa[7*136] = to_tf32(ra1.w);
            float* pb = &Bs[buf][lc8][lrow];
            pb[0*136] = to_tf32(rb0.x); pb[1*136] = to_tf32(rb0.y);
            pb[2*136] = to_tf32(rb0.z); pb[3*136] = to_tf32(rb0.w);
            pb[4*136] = to_tf32(rb1.x); pb[5*136] = to_tf32(rb1.y);
            pb[6*136] = to_tf32(rb1.z); pb[7*136] = to_tf32(rb1.w);
        }
        if (s + 1 < S) {
            const float* a2 = Ag + (s + 1) * 16;
            const float* b2 = Bg + (s + 1) * 16;
            ra0 = *(const float4*)(a2);     ra1 = *(const float4*)(a2 + 4);
            rb0 = *(const float4*)(b2);     rb1 = *(const float4*)(b2 + 4);
        }
        __syncthreads();
#pragma unroll
        for (int kc = 0; kc < 16; kc += 8) {
            uint32_t af[4][4], bf[4][2];
#pragma unroll
            for (int mt = 0; mt < 4; mt++) {
                int r = wm * 64 + mt * 16 + g;
                af[mt][0] = __float_as_uint(As[buf][kc + q][r]);
                af[mt][1] = __float_as_uint(As[buf][kc + q][r + 8]);
                af[mt][2] = __float_as_uint(As[buf][kc + q + 4][r]);
                af[mt][3] = __float_as_uint(As[buf][kc + q + 4][r + 8]);
            }
#pragma unroll
            for (int nt = 0; nt < 4; nt++) {
                int c = wn * 32 + nt * 8 + g;
                bf[nt][0] = __float_as_uint(Bs[buf][kc + q][c]);
                bf[nt][1] = __float_as_uint(Bs[buf][kc + q + 4][c]);
            }
#pragma unroll
            for (int mt = 0; mt < 4; mt++)
#pragma unroll
                for (int nt = 0; nt < 4; nt++)
                    mma_tf32(acc[mt][nt], af[mt], bf[nt]);
        }
        __syncthreads();
    }
#pragma unroll
    for (int mt = 0; mt < 4; mt++)
#pragma unroll
        for (int nt = 0; nt < 4; nt++) {
            int r = m0 + wm * 64 + mt * 16 + g;
            int c = n0 + wn * 32 + nt * 8 + q * 2;
            *(float2*)&C[(size_t)r * N + c] =
                make_float2(acc[mt][nt][0], acc[mt][nt][1]);
            *(float2*)&C[(size_t)(r + 8) * N + c] =
                make_float2(acc[mt][nt][2], acc[mt][nt][3]);
        }
}

// ---------------------------------------------------------------------------
// Phase B tile primitive: 64x64 tile, 256 threads (one half-block), 4x4
// microtile, double-buffered smem, ONE __syncthreads per 16-k slab.
// MODE 0 NT: A[m,k],B[n,k]; MODE 1 NN: A[m,k],B[k,n]; MODE 2 TN: A[k,m],B[k,n]
// ---------------------------------------------------------------------------
template <int MODE>
__device__ __forceinline__ void tile_db(
    const float* __restrict__ A, const float* __restrict__ B, float* hsm,
    int lda, int ldb, int m0, int n0, int kbeg, int kend, int htid,
    float (&acc)[4][4])
{
    float* smA = hsm;
    float* smB = hsm + 2 * SLAB;
    const int rowm = htid >> 2,  c4m = (htid & 3) * 4;
    const int krow = htid >> 4,  c4k = (htid & 15) * 4;
    const int tx = htid & 15,    ty = htid >> 4;
    const int nslab = (kend - kbeg) >> 4;
    float4 ra, rb;

    {
        int k0 = kbeg;
        ra = (MODE == 2) ? *(const float4*)(A + (size_t)(k0 + krow) * lda + m0 + c4k)
                         : *(const float4*)(A + (size_t)(m0 + rowm) * lda + k0 + c4m);
        rb = (MODE == 0) ? *(const float4*)(B + (size_t)(n0 + rowm) * ldb + k0 + c4m)
                         : *(const float4*)(B + (size_t)(k0 + krow) * ldb + n0 + c4k);
    }
    for (int s = 0; s < nslab; s++) {
        const int buf = s & 1;
        {
            float* dA = smA + buf * SLAB;
            float* dB = smB + buf * SLAB;
            if (MODE == 2) { *(float4*)(dA + krow * SL + c4k) = ra; }
            else {
                dA[(c4m + 0) * SL + rowm] = ra.x; dA[(c4m + 1) * SL + rowm] = ra.y;
                dA[(c4m + 2) * SL + rowm] = ra.z; dA[(c4m + 3) * SL + rowm] = ra.w;
            }
            if (MODE == 0) {
                dB[(c4m + 0) * SL + rowm] = rb.x; dB[(c4m + 1) * SL + rowm] = rb.y;
                dB[(c4m + 2) * SL + rowm] = rb.z; dB[(c4m + 3) * SL + rowm] = rb.w;
            } else { *(float4*)(dB + krow * SL + c4k) = rb; }
        }
        if (s + 1 < nslab) {
            int k0 = kbeg + (s + 1) * 16;
            ra = (MODE == 2) ? *(const float4*)(A + (size_t)(k0 + krow) * lda + m0 + c4k)
                             : *(const float4*)(A + (size_t)(m0 + rowm) * lda + k0 + c4m);
            rb = (MODE == 0) ? *(const float4*)(B + (size_t)(n0 + rowm) * ldb + k0 + c4m)
                             : *(const float4*)(B + (size_t)(k0 + krow) * ldb + n0 + c4k);
        }
        __syncthreads();
        const float* cA = smA + buf * SLAB;
        const float* cB = smB + buf * SLAB;
#pragma unroll
        for (int k = 0; k < 16; k++) {
            float4 a = *(const float4*)(cA + k * SL + ty * 4);
            float4 b = *(const float4*)(cB + k * SL + tx * 4);
            float av[4] = {a.x, a.y, a.z, a.w};
            float bv[4] = {b.x, b.y, b.z, b.w};
#pragma unroll
            for (int i = 0; i < 4; i++)
#pragma unroll
                for (int j = 0; j < 4; j++) acc[i][j] += av[i] * bv[j];
        }
        __syncthreads();
    }
}

// ---------------------------------------------------------------------------
// Persistent Phase B kernel: 512 threads, two 64x64 tile-units per block.
// ---------------------------------------------------------------------------
__global__ __launch_bounds__(512, 1) void ttt_persistent(float* __restrict__ out,
                                                         int nb)
{
    __shared__ __align__(16) float PB[2][4 * SLAB];
    const int bid = blockIdx.x, tid = threadIdx.x;
    const int half = tid >> 8, htid = tid & 255;
    const int tx = htid & 15, ty = htid >> 4;
    float* hsm = PB[half];
    const int ustride = nb * 2;
    const int ubase = bid * 2 + half;
    const int gw = (bid * 512 + tid) >> 5, lane = tid & 31;

    for (int step = 0; step <= T_; step++) {
        // ---- R0a: S10 of step-1: out[t-1] = Qt + h2@W2^T + b2 (64 units) ----
        if (step > 0) {
            const int t = step - 1;
            const float* Qt = g_Q + (size_t)t * NH;
            float* od = out + (size_t)t * NH;
            for (int u = ubase; u < 64; u += ustride) {
                int m0 = (u & 3) * 64, n0 = (u >> 2) * 64;
                float acc[4][4] = {};
                tile_db<0>(g_h2, g_W2, hsm, H4, H4, m0, n0, 0, H4, htid, acc);
                int n = n0 + tx * 4;
                float4 bb = *(const float4*)(g_b2 + n);
#pragma unroll
                for (int r = 0; r < 4; r++) {
                    int m = m0 + ty * 4 + r;
                    float4 qv = *(const float4*)(Qt + (size_t)m * HH + n);
                    *(float4*)(od + (size_t)m * HH + n) = make_float4(
                        qv.x + acc[r][0] + bb.x, qv.y + acc[r][1] + bb.y,
                        qv.z + acc[r][2] + bb.z, qv.w + acc[r][3] + bb.w);
                }
            }
        }
        // ---- R0b: S1 split-K partials: Zt @ W1^T (128 units) ----
        if (step < T_) {
            const float* Zt = g_Z + (size_t)step * NH;
            for (int u = ubase; u < 128; u += ustride) {
                int sk = u & 7, tile = u >> 3;
                int m0 = (tile & 3) * 64, n0 = (tile >> 2) * 64;
                float acc[4][4] = {};
                tile_db<0>(Zt, g_W1, hsm, DD, DD, m0, n0, sk * 128, sk * 128 + 128,
                           htid, acc);
                float* cp = g_part + (size_t)sk * MN;
#pragma unroll
                for (int r = 0; r < 4; r++)
                    *(float4*)(cp + (size_t)(m0 + ty * 4 + r) * H4 + n0 + tx * 4) =
                        make_float4(acc[r][0], acc[r][1], acc[r][2], acc[r][3]);
            }
        }
        grid_sync(nb);
        if (step == T_) break;

        const int t = step;
        const float* Zt = g_Z + (size_t)t * NH;
        const float* Yt = g_Y + (size_t)t * NH;
        const float* Qt = g_Q + (size_t)t * NH;

        // ---- R1: a = sum(part)+b1; h = gelu(a) ----
        for (int idx = bid * 512 + tid; idx < MN; idx += nb * 512) {
            float s = 0.f;
#pragma unroll
            for (int z = 0; z < 8; z++) s += g_part[(size_t)z * MN + idx];
            s += g_b1[idx & (H4 - 1)];
            g_a[idx] = s;
            g_h[idx] = gelu_f(s);
        }
        grid_sync(nb);

        // ---- R2: dr = C2*(Zt + h@W2^T + b2 - Yt) (64 units, OLD W2) ----
        for (int u = ubase; u < 64; u += ustride) {
            int m0 = (u & 3) * 64, n0 = (u >> 2) * 64;
            float acc[4][4] = {};
            tile_db<0>(g_h, g_W2, hsm, H4, H4, m0, n0, 0, H4, htid, acc);
            int n = n0 + tx * 4;
            float4 bb = *(const float4*)(g_b2 + n);
#pragma unroll
            for (int r = 0; r < 4; r++) {
                int m = m0 + ty * 4 + r;
                float4 zz = *(const float4*)(Zt + (size_t)m * HH + n);
                float4 yy = *(const float4*)(Yt + (size_t)m * HH + n);
                *(float4*)(g_dr + (size_t)m * HH + n) = make_float4(
                    C2 * (zz.x + acc[r][0] + bb.x - yy.x),
                    C2 * (zz.y + acc[r][1] + bb.y - yy.y),
                    C2 * (zz.z + acc[r][2] + bb.z - yy.z),
                    C2 * (zz.w + acc[r][3] + bb.w - yy.w));
            }
        }
        grid_sync(nb);

        // ---- R3: da_pre partials = dr @ W2 (NN, 128 units, OLD W2) ----
        for (int u = ubase; u < 128; u += ustride) {
            int sk = u & 7, tile = u >> 3;
            int m0 = (tile & 3) * 64, n0 = (tile >> 2) * 64;
            float acc[4][4] = {};
            tile_db<1>(g_dr, g_W2, hsm, HH, H4, m0, n0, sk * 128, sk * 128 + 128,
                       htid, acc);
            float* cp = g_part + (size_t)sk * MN;
#pragma unroll
            for (int r = 0; r < 4; r++)
                *(float4*)(cp + (size_t)(m0 + ty * 4 + r) * H4 + n0 + tx * 4) =
                    make_float4(acc[r][0], acc[r][1], acc[r][2], acc[r][3]);
        }
        grid_sync(nb);

        // ---- R4: da = sum(part) * gelu'(a) ----
        for (int idx = bid * 512 + tid; idx < MN; idx += nb * 512) {
            float s = 0.f;
#pragma unroll
            for (int z = 0; z < 8; z++) s += g_part[(size_t)z * MN + idx];
            g_da[idx] = s * gelu_grad(g_a[idx]);
        }
        grid_sync(nb);

        // ---- R5: W2/W1 updates (128 TN units, Kn=256) + bias colsums ----
        for (int u = ubase; u < 128; u += ustride) {
            if (u < 64) {
                int i0 = (u & 15) * 64, j0 = (u >> 4) * 64;
                float acc[4][4] = {};
                tile_db<2>(g_dr, g_h, hsm, HH, H4, i0, j0, 0, NB, htid, acc);
#pragma unroll
                for (int r = 0; r < 4; r++) {
                    float* pp = g_W2 + (size_t)(i0 + ty * 4 + r) * H4 + j0 + tx * 4;
                    float4 o = *(float4*)pp;
                    o.x -= LR * acc[r][0]; o.y -= LR * acc[r][1];
                    o.z -= LR * acc[r][2]; o.w -= LR * acc[r][3];
                    *(float4*)pp = o;
                }
            } else {
                int v = u - 64;
                int j0 = (v & 3) * 64, i0 = (v >> 2) * 64;
                float acc[4][4] = {};
                tile_db<2>(g_da, Zt, hsm, H4, DD, j0, i0, 0, NB, htid, acc);
#pragma unroll
                for (int r = 0; r < 4; r++) {
                    float* pp = g_W1 + (size_t)(j0 + ty * 4 + r) * DD + i0 + tx * 4;
                    float4 o = *(float4*)pp;
                    o.x -= LR * acc[r][0]; o.y -= LR * acc[r][1];
                    o.z -= LR * acc[r][2]; o.w -= LR * acc[r][3];
                    *(float4*)pp = o;
                }
            }
        }
        // bias updates: warp-parallel column sums
        for (int c = gw; c < HH; c += nb * 16) {
            float s = 0.f;
            for (int n = lane; n < NB; n += 32) s += g_dr[(size_t)n * HH + c];
#pragma unroll
            for (int o = 16; o > 0; o >>= 1) s += __shfl_xor_sync(0xffffffffu, s, o);
            if (lane == 0) g_b2[c] -= LR * s;
        }
        for (int c = gw; c < H4; c += nb * 16) {
            float s = 0.f;
            for (int n = lane; n < NB; n += 32) s += g_da[(size_t)n * H4 + c];
#pragma unroll
            for (int o = 16; o > 0; o >>= 1) s += __shfl_xor_sync(0xffffffffu, s, o);
            if (lane == 0) g_b1[c] -= LR * s;
        }
        grid_sync(nb);

        // ---- R6: a2 partials = Qt @ W1_new^T (128 units) ----
        for (int u = ubase; u < 128; u += ustride) {
            int sk = u & 7, tile = u >> 3;
            int m0 = (tile & 3) * 64, n0 = (tile >> 2) * 64;
            float acc[4][4] = {};
            tile_db<0>(Qt, g_W1, hsm, DD, DD, m0, n0, sk * 128, sk * 128 + 128,
                       htid, acc);
            float* cp = g_part + (size_t)sk * MN;
#pragma unroll
            for (int r = 0; r < 4; r++)
                *(float4*)(cp + (size_t)(m0 + ty * 4 + r) * H4 + n0 + tx * 4) =
                    make_float4(acc[r][0], acc[r][1], acc[r][2], acc[r][3]);
        }
        grid_sync(nb);

        // ---- R7: h2 = gelu(sum(part) + b1_new) ----
        for (int idx = bid * 512 + tid; idx < MN; idx += nb * 512) {
            float s = 0.f;
#pragma unroll
            for (int z = 0; z < 8; z++) s += g_part[(size_t)z * MN + idx];
            s += g_b1[idx & (H4 - 1)];
            g_h2[idx] = gelu_f(s);
        }
        grid_sync(nb);
    }
}

// ---------------------------------------------------------------------------
// kernel_launch
// ---------------------------------------------------------------------------
extern "C" void kernel_launch(void* const* d_in, const int* in_sizes, int n_in,
                              void* d_out, int out_size)
{
    (void)in_sizes; (void)n_in; (void)out_size;
    const float* in_seq = (const float*)d_in[0];
    const float* t_k = (const float*)d_in[1];
    const float* t_v = (const float*)d_in[2];
    const float* t_q = (const float*)d_in[3];

    float *Z, *Y, *Q, *W1, *b1, *W2, *b2;
    cudaGetSymbolAddress((void**)&Z, g_Z);
    cudaGetSymbolAddress((void**)&Y, g_Y);
    cudaGetSymbolAddress((void**)&Q, g_Q);
    cudaGetSymbolAddress((void**)&W1, g_W1);
    cudaGetSymbolAddress((void**)&b1, g_b1);
    cudaGetSymbolAddress((void**)&W2, g_W2);
    cudaGetSymbolAddress((void**)&b2, g_b2);

    cudaMemcpyAsync(W1, d_in[4], sizeof(float) * H4 * HH, cudaMemcpyDeviceToDevice, 0);
    cudaMemcpyAsync(b1, d_in[5], sizeof(float) * H4, cudaMemcpyDeviceToDevice, 0);
    cudaMemcpyAsync(W2, d_in[6], sizeof(float) * HH * H4, cudaMemcpyDeviceToDevice, 0);
    cudaMemcpyAsync(b2, d_in[7], sizeof(float) * HH, cudaMemcpyDeviceToDevice, 0);

    // Phase A: tf32 tensor-core GEMMs
    const int M_big = T_ * NB;
    dim3 gA(M_big / 128, HH / 128);
    gemm_nt_tf32<<<gA, 256>>>(in_seq, t_k, Z, M_big, HH, DD);
    gemm_nt_tf32<<<gA, 256>>>(in_seq, t_v, Y, M_big, HH, DD);
    gemm_nt_tf32<<<gA, 256>>>(in_seq, t_q, Q, M_big, HH, DD);

    // Phase B: one persistent kernel, exactly one block per SM.
    int sms = 0;
    cudaDeviceGetAttribute(&sms, cudaDevAttrMultiProcessorCount, 0);
    if (sms <= 0 || sms > 148) sms = 148;
    ttt_persistent<<<sms, 512>>>((float*)d_out, sms);
}

// round 8
// speedup vs baseline: 1.2326x; 1.2314x over previous
#include <cuda_runtime.h>
#include <cuda_bf16.h>
#include <cstdint>
#include <cstddef>

// ---------------------------------------------------------------------------
// TTLinear. Phase A: 3 big tf32 tensor-core GEMMs. Phase B: one persistent
// kernel, 128 sequential SGD steps, 8 grid barriers/step.
// R8 change: ONE tile-unit per 512-thread block (R6's half-pairing left 84 of
// 148 SMs idle per GEMM region and halved throughput on the rest). K=256
// regions use 32x64 tiles so every GEMM region is ~128 uniform units = 1 wave.
// ---------------------------------------------------------------------------

constexpr int T_  = 128;
constexpr int NB  = 256;
constexpr int DD  = 1024;
constexpr int HH  = 1024;
constexpr int H4  = 256;
constexpr int NH  = NB * HH;    // 262144
constexpr int MN  = NB * H4;    // 65536
constexpr float LR = 1e-3f;
constexpr float C2 = 2.0f / (float)(NB * HH);

constexpr int SL   = 68;        // padded smem row stride (floats); 68*4=272B, 16B-aligned
constexpr int SLAB = 16 * SL;   // one k-slab

// ------------------------- device scratch ----------------------------------
__device__ float g_Z[(size_t)T_ * NH];
__device__ float g_Y[(size_t)T_ * NH];
__device__ float g_Q[(size_t)T_ * NH];
__device__ float g_W1[H4 * HH];
__device__ float g_b1[H4];
__device__ float g_W2[HH * H4];
__device__ float g_b2[HH];
__device__ float g_a[MN];
__device__ float g_h[MN];
__device__ float g_h2[MN];
__device__ float g_da[MN];
__device__ float g_dr[NB * HH];
__device__ float g_part[8 * MN];

// barrier state on separate cache lines
__device__ __align__(128) unsigned g_cnt = 0;
__device__ __align__(128) unsigned g_gen = 0;

// ------------------------------ helpers ------------------------------------
__device__ __forceinline__ float gelu_f(float x) {
    return 0.5f * x * (1.0f + erff(x * 0.70710678118654752f));
}
__device__ __forceinline__ float gelu_grad(float x) {
    float cdf = 0.5f * (1.0f + erff(x * 0.70710678118654752f));
    float pdf = 0.3989422804014327f * expf(-0.5f * x * x);
    return cdf + x * pdf;
}
__device__ __forceinline__ float to_tf32(float x) {
    uint32_t u;
    asm("cvt.rna.tf32.f32 %0, %1;" : "=r"(u) : "f"(x));
    return __uint_as_float(u);
}
__device__ __forceinline__ void mma_tf32(float (&c)[4], const uint32_t (&a)[4],
                                         const uint32_t (&b)[2]) {
    asm volatile(
        "mma.sync.aligned.m16n8k8.row.col.f32.tf32.tf32.f32 "
        "{%0,%1,%2,%3}, {%4,%5,%6,%7}, {%8,%9}, {%0,%1,%2,%3};"
        : "+f"(c[0]), "+f"(c[1]), "+f"(c[2]), "+f"(c[3])
        : "r"(a[0]), "r"(a[1]), "r"(a[2]), "r"(a[3]), "r"(b[0]), "r"(b[1]));
}

// Hot-spin grid barrier, bounded (sync bug -> wrong output, not a hang).
__device__ __forceinline__ void grid_sync(unsigned nb) {
    __syncthreads();
    if (threadIdx.x == 0) {
        unsigned gen = *(volatile unsigned*)&g_gen;
        __threadfence();
        if (atomicAdd(&g_cnt, 1) == nb - 1) {
            g_cnt = 0;
            __threadfence();
            atomicAdd(&g_gen, 1);
        } else {
            for (int spin = 0; spin < 1000000; spin++) {
                if (*(volatile unsigned*)&g_gen != gen) break;
            }
        }
        __threadfence();
    }
    __syncthreads();
}

// ---------------------------------------------------------------------------
// Phase A: C[M,N] = A[M,K] @ B[N,K]^T via tf32 mma.sync (unchanged from R7).
// ---------------------------------------------------------------------------
__global__ __launch_bounds__(256, 2) void gemm_nt_tf32(
    const float* __restrict__ A, const float* __restrict__ B,
    float* __restrict__ C, int M, int N, int K)
{
    __shared__ float As[2][16][136];
    __shared__ float Bs[2][16][136];
    const int m0 = blockIdx.x * 128, n0 = blockIdx.y * 128;
    const int tid = threadIdx.x;
    const int lrow = tid & 127, lc8 = (tid >> 7) * 8;
    const int w = tid >> 5, lane = tid & 31;
    const int wm = w >> 2, wn = w & 3;
    const int g = lane >> 2, q = lane & 3;

    float acc[4][4][4] = {};
    const float* Ag = A + (size_t)(m0 + lrow) * K + lc8;
    const float* Bg = B + (size_t)(n0 + lrow) * K + lc8;

    float4 ra0 = *(const float4*)(Ag);
    float4 ra1 = *(const float4*)(Ag + 4);
    float4 rb0 = *(const float4*)(Bg);
    float4 rb1 = *(const float4*)(Bg + 4);

    const int S = K / 16;
    for (int s = 0; s < S; s++) {
        const int buf = s & 1;
        {
            float* pa = &As[buf][lc8][lrow];
            pa[0*136] = to_tf32(ra0.x); pa[1*136] = to_tf32(ra0.y);
            pa[2*136] = to_tf32(ra0.z); pa[3*136] = to_tf32(ra0.w);
            pa[4*136] = to_tf32(ra1.x); pa[5*136] = to_tf32(ra1.y);
            pa[6*136] = to_tf32(ra1.z); pa[7*136] = to_tf32(ra1.w);
            float* pb = &Bs[buf][lc8][lrow];
            pb[0*136] = to_tf32(rb0.x); pb[1*136] = to_tf32(rb0.y);
            pb[2*136] = to_tf32(rb0.z); pb[3*136] = to_tf32(rb0.w);
            pb[4*136] = to_tf32(rb1.x); pb[5*136] = to_tf32(rb1.y);
            pb[6*136] = to_tf32(rb1.z); pb[7*136] = to_tf32(rb1.w);
        }
        if (s + 1 < S) {
            const float* a2 = Ag + (s + 1) * 16;
            const float* b2 = Bg + (s + 1) * 16;
            ra0 = *(const float4*)(a2);     ra1 = *(const float4*)(a2 + 4);
            rb0 = *(const float4*)(b2);     rb1 = *(const float4*)(b2 + 4);
        }
        __syncthreads();
#pragma unroll
        for (int kc = 0; kc < 16; kc += 8) {
            uint32_t af[4][4], bf[4][2];
#pragma unroll
            for (int mt = 0; mt < 4; mt++) {
                int r = wm * 64 + mt * 16 + g;
                af[mt][0] = __float_as_uint(As[buf][kc + q][r]);
                af[mt][1] = __float_as_uint(As[buf][kc + q][r + 8]);
                af[mt][2] = __float_as_uint(As[buf][kc + q + 4][r]);
                af[mt][3] = __float_as_uint(As[buf][kc + q + 4][r + 8]);
            }
#pragma unroll
            for (int nt = 0; nt < 4; nt++) {
                int c = wn * 32 + nt * 8 + g;
                bf[nt][0] = __float_as_uint(Bs[buf][kc + q][c]);
                bf[nt][1] = __float_as_uint(Bs[buf][kc + q + 4][c]);
            }
#pragma unroll
            for (int mt = 0; mt < 4; mt++)
#pragma unroll
                for (int nt = 0; nt < 4; nt++)
                    mma_tf32(acc[mt][nt], af[mt], bf[nt]);
        }
        __syncthreads();
    }
#pragma unroll
    for (int mt = 0; mt < 4; mt++)
#pragma unroll
        for (int nt = 0; nt < 4; nt++) {
            int r = m0 + wm * 64 + mt * 16 + g;
            int c = n0 + wn * 32 + nt * 8 + q * 2;
            *(float2*)&C[(size_t)r * N + c] =
                make_float2(acc[mt][nt][0], acc[mt][nt][1]);
            *(float2*)&C[(size_t)(r + 8) * N + c] =
                make_float2(acc[mt][nt][2], acc[mt][nt][3]);
        }
}

// ---------------------------------------------------------------------------
// Phase B tile primitive: TM x 64 tile (TM=32 or 64), 512 threads per unit,
// double-buffered, one sync pair per 16-k slab.
// MODE 0 NT: A[m,k],B[n,k]; MODE 1 NN: A[m,k],B[k,n]; MODE 2 TN: A[k,m],B[k,n]
// Thread map: tx=tid&15 (4 cols), ty=tid>>4 (TM/32 rows).
// ---------------------------------------------------------------------------
template <int MODE, int TM>
__device__ __forceinline__ void tile512(
    const float* __restrict__ A, const float* __restrict__ B, float* sm,
    int lda, int ldb, int m0, int n0, int kbeg, int kend,
    float (&acc)[2][4])
{
    const int tid = threadIdx.x;
    const int tx = tid & 15, ty = tid >> 4;
    float* smA = sm;
    float* smB = sm + 2 * SLAB;
    const int nslab = (kend - kbeg) >> 4;

    float a0, a1, b0, b1;

    auto fetch = [&](int k0) {
        if (MODE == 2) {              // A[k,m]
            const float* p = A + (size_t)(k0 + (tid >> 5)) * lda + m0;
            if (TM == 64) { float2 v = *(const float2*)(p + (tid & 31) * 2); a0 = v.x; a1 = v.y; }
            else          { a0 = p[tid & 31]; }
        } else {                      // A[m,k]
            if (TM == 64) {
                float2 v = *(const float2*)(A + (size_t)(m0 + (tid >> 3)) * lda + k0 + (tid & 7) * 2);
                a0 = v.x; a1 = v.y;
            } else {
                a0 = A[(size_t)(m0 + (tid >> 4)) * lda + k0 + (tid & 15)];
            }
        }
        if (MODE == 0) {              // B[n,k]
            float2 v = *(const float2*)(B + (size_t)(n0 + (tid >> 3)) * ldb + k0 + (tid & 7) * 2);
            b0 = v.x; b1 = v.y;
        } else {                      // B[k,n]
            float2 v = *(const float2*)(B + (size_t)(k0 + (tid >> 5)) * ldb + n0 + (tid & 31) * 2);
            b0 = v.x; b1 = v.y;
        }
    };
    auto store = [&](int buf) {
        float* dA = smA + buf * SLAB;
        float* dB = smB + buf * SLAB;
        if (MODE == 2) {
            if (TM == 64) *(float2*)(dA + (tid >> 5) * SL + (tid & 31) * 2) = make_float2(a0, a1);
            else          dA[(tid >> 5) * SL + (tid & 31)] = a0;
        } else {
            if (TM == 64) {
                int r = tid >> 3, c = (tid & 7) * 2;
                dA[c * SL + r] = a0; dA[(c + 1) * SL + r] = a1;
            } else {
                dA[(tid & 15) * SL + (tid >> 4)] = a0;
            }
        }
        if (MODE == 0) {
            int r = tid >> 3, c = (tid & 7) * 2;
            dB[c * SL + r] = b0; dB[(c + 1) * SL + r] = b1;
        } else {
            *(float2*)(dB + (tid >> 5) * SL + (tid & 31) * 2) = make_float2(b0, b1);
        }
    };

    fetch(kbeg);
    for (int s = 0; s < nslab; s++) {
        const int buf = s & 1;
        store(buf);
        if (s + 1 < nslab) fetch(kbeg + (s + 1) * 16);
        __syncthreads();
        const float* cA = smA + buf * SLAB;
        const float* cB = smB + buf * SLAB;
#pragma unroll
        for (int k = 0; k < 16; k++) {
            float4 b = *(const float4*)(cB + k * SL + tx * 4);
            if (TM == 64) {
                float2 a = *(const float2*)(cA + k * SL + ty * 2);
#pragma unroll
                for (int j = 0; j < 4; j++) {
                    float bj = (&b.x)[j];
                    acc[0][j] += a.x * bj;
                    acc[1][j] += a.y * bj;
                }
            } else {
                float a = cA[k * SL + ty];
#pragma unroll
                for (int j = 0; j < 4; j++) acc[0][j] += a * (&b.x)[j];
            }
        }
        __syncthreads();
    }
}

// ---------------------------------------------------------------------------
// Persistent Phase B kernel: 512 threads, ONE tile-unit per block per wave.
// ---------------------------------------------------------------------------
__global__ __launch_bounds__(512, 1) void ttt_persistent(float* __restrict__ out,
                                                         int nb)
{
    __shared__ __align__(16) float SM[4 * SLAB];
    const int bid = blockIdx.x, tid = threadIdx.x;
    const int tx = tid & 15, ty = tid >> 4;
    const int gw = (bid * 512 + tid) >> 5, lane = tid & 31;

    for (int step = 0; step <= T_; step++) {
        // ---- R0: S10 of step-1 (128 units, 32x64, K=256)
        //        + S1 partials of step (128 units, 64x64, K=128 split) ----
        {
            const int nA = (step > 0) ? 128 : 0;
            const int nTot = nA + ((step < T_) ? 128 : 0);
            for (int u = bid; u < nTot; u += nb) {
                int uu = (step > 0) ? u : u + 128;
                if (uu < 128) {
                    // S10: out[t-1] = Qt + h2 @ W2^T + b2
                    const int t = step - 1;
                    const float* Qt = g_Q + (size_t)t * NH;
                    float* od = out + (size_t)t * NH;
                    int m0 = (uu & 7) * 32, n0 = (uu >> 3) * 64;
                    float acc[2][4] = {};
                    tile512<0, 32>(g_h2, g_W2, SM, H4, H4, m0, n0, 0, H4, acc);
                    int n = n0 + tx * 4, m = m0 + ty;
                    float4 bb = *(const float4*)(g_b2 + n);
                    float4 qv = *(const float4*)(Qt + (size_t)m * HH + n);
                    *(float4*)(od + (size_t)m * HH + n) = make_float4(
                        qv.x + acc[0][0] + bb.x, qv.y + acc[0][1] + bb.y,
                        qv.z + acc[0][2] + bb.z, qv.w + acc[0][3] + bb.w);
                } else {
                    // S1: part[sk] = Zt @ W1^T (k slice)
                    int v = uu - 128;
                    const float* Zt = g_Z + (size_t)step * NH;
                    int sk = v & 7, tile = v >> 3;
                    int m0 = (tile & 3) * 64, n0 = (tile >> 2) * 64;
                    float acc[2][4] = {};
                    tile512<0, 64>(Zt, g_W1, SM, DD, DD, m0, n0,
                                   sk * 128, sk * 128 + 128, acc);
                    float* cp = g_part + (size_t)sk * MN;
#pragma unroll
                    for (int r = 0; r < 2; r++)
                        *(float4*)(cp + (size_t)(m0 + ty * 2 + r) * H4 + n0 + tx * 4) =
                            make_float4(acc[r][0], acc[r][1], acc[r][2], acc[r][3]);
                }
            }
        }
        grid_sync(nb);
        if (step == T_) break;

        const int t = step;
        const float* Zt = g_Z + (size_t)t * NH;
        const float* Yt = g_Y + (size_t)t * NH;
        const float* Qt = g_Q + (size_t)t * NH;

        // ---- R1: a = sum(part)+b1; h = gelu(a) ----
        for (int idx = bid * 512 + tid; idx < MN; idx += nb * 512) {
            float s = 0.f;
#pragma unroll
            for (int z = 0; z < 8; z++) s += g_part[(size_t)z * MN + idx];
            s += g_b1[idx & (H4 - 1)];
            g_a[idx] = s;
            g_h[idx] = gelu_f(s);
        }
        grid_sync(nb);

        // ---- R2: dr = C2*(Zt + h@W2^T + b2 - Yt) (128 units, 32x64, OLD W2) ----
        for (int u = bid; u < 128; u += nb) {
            int m0 = (u & 7) * 32, n0 = (u >> 3) * 64;
            float acc[2][4] = {};
            tile512<0, 32>(g_h, g_W2, SM, H4, H4, m0, n0, 0, H4, acc);
            int n = n0 + tx * 4, m = m0 + ty;
            float4 bb = *(const float4*)(g_b2 + n);
            float4 zz = *(const float4*)(Zt + (size_t)m * HH + n);
            float4 yy = *(const float4*)(Yt + (size_t)m * HH + n);
            *(float4*)(g_dr + (size_t)m * HH + n) = make_float4(
                C2 * (zz.x + acc[0][0] + bb.x - yy.x),
                C2 * (zz.y + acc[0][1] + bb.y - yy.y),
                C2 * (zz.z + acc[0][2] + bb.z - yy.z),
                C2 * (zz.w + acc[0][3] + bb.w - yy.w));
        }
        grid_sync(nb);

        // ---- R3: da_pre partials = dr @ W2 (NN, 128 units, 64x64, OLD W2) ----
        for (int u = bid; u < 128; u += nb) {
            int sk = u & 7, tile = u >> 3;
            int m0 = (tile & 3) * 64, n0 = (tile >> 2) * 64;
            float acc[2][4] = {};
            tile512<1, 64>(g_dr, g_W2, SM, HH, H4, m0, n0,
                           sk * 128, sk * 128 + 128, acc);
            float* cp = g_part + (size_t)sk * MN;
#pragma unroll
            for (int r = 0; r < 2; r++)
                *(float4*)(cp + (size_t)(m0 + ty * 2 + r) * H4 + n0 + tx * 4) =
                    make_float4(acc[r][0], acc[r][1], acc[r][2], acc[r][3]);
        }
        grid_sync(nb);

        // ---- R4: da = sum(part) * gelu'(a) ----
        for (int idx = bid * 512 + tid; idx < MN; idx += nb * 512) {
            float s = 0.f;
#pragma unroll
            for (int z = 0; z < 8; z++) s += g_part[(size_t)z * MN + idx];
            g_da[idx] = s * gelu_grad(g_a[idx]);
        }
        grid_sync(nb);

        // ---- R5: weight updates (128 TN units, 64x64, Kn=256) + biases ----
        for (int u = bid; u < 128; u += nb) {
            if (u < 64) {
                // W2[i,j] -= LR * sum_n dr[n,i] h[n,j]
                int i0 = (u & 15) * 64, j0 = (u >> 4) * 64;
                float acc[2][4] = {};
                tile512<2, 64>(g_dr, g_h, SM, HH, H4, i0, j0, 0, NB, acc);
#pragma unroll
                for (int r = 0; r < 2; r++) {
                    float* pp = g_W2 + (size_t)(i0 + ty * 2 + r) * H4 + j0 + tx * 4;
                    float4 o = *(float4*)pp;
                    o.x -= LR * acc[r][0]; o.y -= LR * acc[r][1];
                    o.z -= LR * acc[r][2]; o.w -= LR * acc[r][3];
                    *(float4*)pp = o;
                }
            } else {
                // W1[j,i] -= LR * sum_n da[n,j] Zt[n,i]
                int v = u - 64;
                int j0 = (v & 3) * 64, i0 = (v >> 2) * 64;
                float acc[2][4] = {};
                tile512<2, 64>(g_da, Zt, SM, H4, DD, j0, i0, 0, NB, acc);
#pragma unroll
                for (int r = 0; r < 2; r++) {
                    float* pp = g_W1 + (size_t)(j0 + ty * 2 + r) * DD + i0 + tx * 4;
                    float4 o = *(float4*)pp;
                    o.x -= LR * acc[r][0]; o.y -= LR * acc[r][1];
                    o.z -= LR * acc[r][2]; o.w -= LR * acc[r][3];
                    *(float4*)pp = o;
                }
            }
        }
        // bias colsums (warp-parallel, no intra-block syncs)
        for (int c = gw; c < HH; c += nb * 16) {
            float s = 0.f;
            for (int n = lane; n < NB; n += 32) s += g_dr[(size_t)n * HH + c];
#pragma unroll
            for (int o = 16; o > 0; o >>= 1) s += __shfl_xor_sync(0xffffffffu, s, o);
            if (lane == 0) g_b2[c] -= LR * s;
        }
        for (int c = gw; c < H4; c += nb * 16) {
            float s = 0.f;
            for (int n = lane; n < NB; n += 32) s += g_da[(size_t)n * H4 + c];
#pragma unroll
            for (int o = 16; o > 0; o >>= 1) s += __shfl_xor_sync(0xffffffffu, s, o);
            if (lane == 0) g_b1[c] -= LR * s;
        }
        grid_sync(nb);

        // ---- R6: a2 partials = Qt @ W1_new^T (128 units, 64x64) ----
        for (int u = bid; u < 128; u += nb) {
            int sk = u & 7, tile = u >> 3;
            int m0 = (tile & 3) * 64, n0 = (tile >> 2) * 64;
            float acc[2][4] = {};
            tile512<0, 64>(Qt, g_W1, SM, DD, DD, m0, n0,
                           sk * 128, sk * 128 + 128, acc);
            float* cp = g_part + (size_t)sk * MN;
#pragma unroll
            for (int r = 0; r < 2; r++)
                *(float4*)(cp + (size_t)(m0 + ty * 2 + r) * H4 + n0 + tx * 4) =
                    make_float4(acc[r][0], acc[r][1], acc[r][2], acc[r][3]);
        }
        grid_sync(nb);

        // ---- R7: h2 = gelu(sum(part) + b1_new) ----
        for (int idx = bid * 512 + tid; idx < MN; idx += nb * 512) {
            float s = 0.f;
#pragma unroll
            for (int z = 0; z < 8; z++) s += g_part[(size_t)z * MN + idx];
            s += g_b1[idx & (H4 - 1)];
            g_h2[idx] = gelu_f(s);
        }
        grid_sync(nb);
    }
}

// ---------------------------------------------------------------------------
// kernel_launch
// ---------------------------------------------------------------------------
extern "C" void kernel_launch(void* const* d_in, const int* in_sizes, int n_in,
                              void* d_out, int out_size)
{
    (void)in_sizes; (void)n_in; (void)out_size;
    const float* in_seq = (const float*)d_in[0];
    const float* t_k = (const float*)d_in[1];
    const float* t_v = (const float*)d_in[2];
    const float* t_q = (const float*)d_in[3];

    float *Z, *Y, *Q, *W1, *b1, *W2, *b2;
    cudaGetSymbolAddress((void**)&Z, g_Z);
    cudaGetSymbolAddress((void**)&Y, g_Y);
    cudaGetSymbolAddress((void**)&Q, g_Q);
    cudaGetSymbolAddress((void**)&W1, g_W1);
    cudaGetSymbolAddress((void**)&b1, g_b1);
    cudaGetSymbolAddress((void**)&W2, g_W2);
    cudaGetSymbolAddress((void**)&b2, g_b2);

    cudaMemcpyAsync(W1, d_in[4], sizeof(float) * H4 * HH, cudaMemcpyDeviceToDevice, 0);
    cudaMemcpyAsync(b1, d_in[5], sizeof(float) * H4, cudaMemcpyDeviceToDevice, 0);
    cudaMemcpyAsync(W2, d_in[6], sizeof(float) * HH * H4, cudaMemcpyDeviceToDevice, 0);
    cudaMemcpyAsync(b2, d_in[7], sizeof(float) * HH, cudaMemcpyDeviceToDevice, 0);

    // Phase A: tf32 tensor-core GEMMs
    const int M_big = T_ * NB;
    dim3 gA(M_big / 128, HH / 128);
    gemm_nt_tf32<<<gA, 256>>>(in_seq, t_k, Z, M_big, HH, DD);
    gemm_nt_tf32<<<gA, 256>>>(in_seq, t_v, Y, M_big, HH, DD);
    gemm_nt_tf32<<<gA, 256>>>(in_seq, t_q, Q, M_big, HH, DD);

    // Phase B: one persistent kernel, exactly one block per SM.
    int sms = 0;
    cudaDeviceGetAttribute(&sms, cudaDevAttrMultiProcessorCount, 0);
    if (sms <= 0 || sms > 148) sms = 148;
    ttt_persistent<<<sms, 512>>>((float*)d_out, sms);
}

// round 9
// speedup vs baseline: 1.5118x; 1.2265x over previous
#include <cuda_runtime.h>
#include <cuda_bf16.h>
#include <cstdint>
#include <cstddef>

// ---------------------------------------------------------------------------
// TTLinear. Phase A: 3 big tf32 tensor-core GEMMs. Phase B: one persistent
// kernel (256 threads/block, one block/SM), 128 sequential SGD steps, 8 grid
// barriers/step. R9: all Phase-B tiles use balanced microtiles (4x4 on 64x64,
// 2x4 on 32x64) so smem feed (128B/cyc) matches the 64 FMA/cyc fp32 pipe.
// ---------------------------------------------------------------------------

constexpr int T_  = 128;
constexpr int NB  = 256;
constexpr int DD  = 1024;
constexpr int HH  = 1024;
constexpr int H4  = 256;
constexpr int NH  = NB * HH;    // 262144
constexpr int MN  = NB * H4;    // 65536
constexpr float LR = 1e-3f;
constexpr float C2 = 2.0f / (float)(NB * HH);

constexpr int SL   = 68;        // padded smem row stride (floats)
constexpr int SLAB = 16 * SL;   // one 16-k slab

// ------------------------- device scratch ----------------------------------
__device__ float g_Z[(size_t)T_ * NH];
__device__ float g_Y[(size_t)T_ * NH];
__device__ float g_Q[(size_t)T_ * NH];
__device__ float g_W1[H4 * HH];
__device__ float g_b1[H4];
__device__ float g_W2[HH * H4];
__device__ float g_b2[HH];
__device__ float g_a[MN];
__device__ float g_h[MN];
__device__ float g_h2[MN];
__device__ float g_da[MN];
__device__ float g_dr[NB * HH];
__device__ float g_part[8 * MN];

__device__ __align__(128) unsigned g_cnt = 0;
__device__ __align__(128) unsigned g_gen = 0;

// ------------------------------ helpers ------------------------------------
__device__ __forceinline__ float gelu_f(float x) {
    return 0.5f * x * (1.0f + erff(x * 0.70710678118654752f));
}
__device__ __forceinline__ float gelu_grad(float x) {
    float cdf = 0.5f * (1.0f + erff(x * 0.70710678118654752f));
    float pdf = 0.3989422804014327f * expf(-0.5f * x * x);
    return cdf + x * pdf;
}
__device__ __forceinline__ float to_tf32(float x) {
    uint32_t u;
    asm("cvt.rna.tf32.f32 %0, %1;" : "=r"(u) : "f"(x));
    return __uint_as_float(u);
}
__device__ __forceinline__ void mma_tf32(float (&c)[4], const uint32_t (&a)[4],
                                         const uint32_t (&b)[2]) {
    asm volatile(
        "mma.sync.aligned.m16n8k8.row.col.f32.tf32.tf32.f32 "
        "{%0,%1,%2,%3}, {%4,%5,%6,%7}, {%8,%9}, {%0,%1,%2,%3};"
        : "+f"(c[0]), "+f"(c[1]), "+f"(c[2]), "+f"(c[3])
        : "r"(a[0]), "r"(a[1]), "r"(a[2]), "r"(a[3]), "r"(b[0]), "r"(b[1]));
}

// Hot-spin grid barrier, bounded (sync bug -> wrong output, not a hang).
__device__ __forceinline__ void grid_sync(unsigned nb) {
    __syncthreads();
    if (threadIdx.x == 0) {
        unsigned gen = *(volatile unsigned*)&g_gen;
        __threadfence();
        if (atomicAdd(&g_cnt, 1) == nb - 1) {
            g_cnt = 0;
            __threadfence();
            atomicAdd(&g_gen, 1);
        } else {
            for (int spin = 0; spin < 1000000; spin++) {
                if (*(volatile unsigned*)&g_gen != gen) break;
            }
        }
        __threadfence();
    }
    __syncthreads();
}

// ---------------------------------------------------------------------------
// Phase A: C[M,N] = A[M,K] @ B[N,K]^T via tf32 mma.sync (unchanged).
// ---------------------------------------------------------------------------
__global__ __launch_bounds__(256, 2) void gemm_nt_tf32(
    const float* __restrict__ A, const float* __restrict__ B,
    float* __restrict__ C, int M, int N, int K)
{
    __shared__ float As[2][16][136];
    __shared__ float Bs[2][16][136];
    const int m0 = blockIdx.x * 128, n0 = blockIdx.y * 128;
    const int tid = threadIdx.x;
    const int lrow = tid & 127, lc8 = (tid >> 7) * 8;
    const int w = tid >> 5, lane = tid & 31;
    const int wm = w >> 2, wn = w & 3;
    const int g = lane >> 2, q = lane & 3;

    float acc[4][4][4] = {};
    const float* Ag = A + (size_t)(m0 + lrow) * K + lc8;
    const float* Bg = B + (size_t)(n0 + lrow) * K + lc8;

    float4 ra0 = *(const float4*)(Ag);
    float4 ra1 = *(const float4*)(Ag + 4);
    float4 rb0 = *(const float4*)(Bg);
    float4 rb1 = *(const float4*)(Bg + 4);

    const int S = K / 16;
    for (int s = 0; s < S; s++) {
        const int buf = s & 1;
        {
            float* pa = &As[buf][lc8][lrow];
            pa[0*136] = to_tf32(ra0.x); pa[1*136] = to_tf32(ra0.y);
            pa[2*136] = to_tf32(ra0.z); pa[3*136] = to_tf32(ra0.w);
            pa[4*136] = to_tf32(ra1.x); pa[5*136] = to_tf32(ra1.y);
            pa[6*136] = to_tf32(ra1.z); pa[7*136] = to_tf32(ra1.w);
            float* pb = &Bs[buf][lc8][lrow];
            pb[0*136] = to_tf32(rb0.x); pb[1*136] = to_tf32(rb0.y);
            pb[2*136] = to_tf32(rb0.z); pb[3*136] = to_tf32(rb0.w);
            pb[4*136] = to_tf32(rb1.x); pb[5*136] = to_tf32(rb1.y);
            pb[6*136] = to_tf32(rb1.z); pb[7*136] = to_tf32(rb1.w);
        }
        if (s + 1 < S) {
            const float* a2 = Ag + (s + 1) * 16;
            const float* b2 = Bg + (s + 1) * 16;
            ra0 = *(const float4*)(a2);     ra1 = *(const float4*)(a2 + 4);
            rb0 = *(const float4*)(b2);     rb1 = *(const float4*)(b2 + 4);
        }
        __syncthreads();
#pragma unroll
        for (int kc = 0; kc < 16; kc += 8) {
            uint32_t af[4][4], bf[4][2];
#pragma unroll
            for (int mt = 0; mt < 4; mt++) {
                int r = wm * 64 + mt * 16 + g;
                af[mt][0] = __float_as_uint(As[buf][kc + q][r]);
                af[mt][1] = __float_as_uint(As[buf][kc + q][r + 8]);
                af[mt][2] = __float_as_uint(As[buf][kc + q + 4][r]);
                af[mt][3] = __float_as_uint(As[buf][kc + q + 4][r + 8]);
            }
#pragma unroll
            for (int nt = 0; nt < 4; nt++) {
                int c = wn * 32 + nt * 8 + g;
                bf[nt][0] = __float_as_uint(Bs[buf][kc + q][c]);
                bf[nt][1] = __float_as_uint(Bs[buf][kc + q + 4][c]);
            }
#pragma unroll
            for (int mt = 0; mt < 4; mt++)
#pragma unroll
                for (int nt = 0; nt < 4; nt++)
                    mma_tf32(acc[mt][nt], af[mt], bf[nt]);
        }
        __syncthreads();
    }
#pragma unroll
    for (int mt = 0; mt < 4; mt++)
#pragma unroll
        for (int nt = 0; nt < 4; nt++) {
            int r = m0 + wm * 64 + mt * 16 + g;
            int c = n0 + wn * 32 + nt * 8 + q * 2;
            *(float2*)&C[(size_t)r * N + c] =
                make_float2(acc[mt][nt][0], acc[mt][nt][1]);
            *(float2*)&C[(size_t)(r + 8) * N + c] =
                make_float2(acc[mt][nt][2], acc[mt][nt][3]);
        }
}

// ---------------------------------------------------------------------------
// Phase B tile: TM x 64 (TM=64: 4x4 micro, TM=32: 2x4 micro), 256 threads,
// double-buffered, one sync pair per 16-k slab. Balanced smem:FMA ratio.
// MODE 0 NT: A[m,k],B[n,k]; MODE 1 NN: A[m,k],B[k,n]; MODE 2 TN: A[k,m],B[k,n]
// Compute map: tx=tid&15 (cols x4), ty=tid>>4 (rows x4 or x2).
// ---------------------------------------------------------------------------
template <int MODE, int TM>
__device__ __forceinline__ void tile256(
    const float* __restrict__ A, const float* __restrict__ B, float* sm,
    int lda, int ldb, int m0, int n0, int kbeg, int kend,
    float (&acc)[4][4])
{
    const int tid = threadIdx.x;
    const int tx = tid & 15, ty = tid >> 4;
    float* smA = sm;
    float* smB = sm + 2 * SLAB;
    const int nslab = (kend - kbeg) >> 4;

    float4 ra, rb;
    float2 ra2;

    auto fetch = [&](int k0) {
        if (MODE == 2) {                       // A[k,m]
            ra = *(const float4*)(A + (size_t)(k0 + (tid >> 4)) * lda + m0 + (tid & 15) * 4);
        } else if (TM == 64) {                 // A[m,k], 64 rows
            ra = *(const float4*)(A + (size_t)(m0 + (tid >> 2)) * lda + k0 + (tid & 3) * 4);
        } else {                               // A[m,k], 32 rows
            ra2 = *(const float2*)(A + (size_t)(m0 + (tid >> 3)) * lda + k0 + (tid & 7) * 2);
        }
        if (MODE == 0) {                       // B[n,k]
            rb = *(const float4*)(B + (size_t)(n0 + (tid >> 2)) * ldb + k0 + (tid & 3) * 4);
        } else {                               // B[k,n]
            rb = *(const float4*)(B + (size_t)(k0 + (tid >> 4)) * ldb + n0 + (tid & 15) * 4);
        }
    };
    auto store = [&](int buf) {
        float* dA = smA + buf * SLAB;
        float* dB = smB + buf * SLAB;
        if (MODE == 2) {
            *(float4*)(dA + (tid >> 4) * SL + (tid & 15) * 4) = ra;
        } else if (TM == 64) {
            int r = tid >> 2, c = (tid & 3) * 4;
            dA[(c + 0) * SL + r] = ra.x; dA[(c + 1) * SL + r] = ra.y;
            dA[(c + 2) * SL + r] = ra.z; dA[(c + 3) * SL + r] = ra.w;
        } else {
            int r = tid >> 3, c = (tid & 7) * 2;
            dA[(c + 0) * SL + r] = ra2.x; dA[(c + 1) * SL + r] = ra2.y;
        }
        if (MODE == 0) {
            int r = tid >> 2, c = (tid & 3) * 4;
            dB[(c + 0) * SL + r] = rb.x; dB[(c + 1) * SL + r] = rb.y;
            dB[(c + 2) * SL + r] = rb.z; dB[(c + 3) * SL + r] = rb.w;
        } else {
            *(float4*)(dB + (tid >> 4) * SL + (tid & 15) * 4) = rb;
        }
    };

    fetch(kbeg);
    for (int s = 0; s < nslab; s++) {
        const int buf = s & 1;
        store(buf);
        if (s + 1 < nslab) fetch(kbeg + (s + 1) * 16);
        __syncthreads();
        const float* cA = smA + buf * SLAB;
        const float* cB = smB + buf * SLAB;
#pragma unroll
        for (int k = 0; k < 16; k++) {
            float4 b = *(const float4*)(cB + k * SL + tx * 4);
            if (TM == 64) {
                float4 a = *(const float4*)(cA + k * SL + ty * 4);
#pragma unroll
                for (int j = 0; j < 4; j++) {
                    float bj = (&b.x)[j];
                    acc[0][j] += a.x * bj;
                    acc[1][j] += a.y * bj;
                    acc[2][j] += a.z * bj;
                    acc[3][j] += a.w * bj;
                }
            } else {
                float2 a = *(const float2*)(cA + k * SL + ty * 2);
#pragma unroll
                for (int j = 0; j < 4; j++) {
                    float bj = (&b.x)[j];
                    acc[0][j] += a.x * bj;
                    acc[1][j] += a.y * bj;
                }
            }
        }
        __syncthreads();
    }
}

// ---------------------------------------------------------------------------
// Persistent Phase B kernel: 256 threads/block, one tile-unit per block/wave.
// ---------------------------------------------------------------------------
__global__ __launch_bounds__(256, 1) void ttt_persistent(float* __restrict__ out,
                                                         int nb)
{
    __shared__ __align__(16) float SM[4 * SLAB];
    const int bid = blockIdx.x, tid = threadIdx.x;
    const int tx = tid & 15, ty = tid >> 4;
    const int gw = (bid * 256 + tid) >> 5, lane = tid & 31;

    for (int step = 0; step <= T_; step++) {
        // ---- R0: S10 of step-1 (128 u, 32x64 NT, K=256)
        //        + S1 partials of step (128 u, 64x64 NT, K=128 split8) ----
        {
            const int nA = (step > 0) ? 128 : 0;
            const int nTot = nA + ((step < T_) ? 128 : 0);
            for (int u = bid; u < nTot; u += nb) {
                const int uu = (step > 0) ? u : u + 128;
                if (uu < 128) {
                    // S10: out[t-1] = Qt + h2 @ W2^T + b2
                    const int t = step - 1;
                    const float* Qt = g_Q + (size_t)t * NH;
                    float* od = out + (size_t)t * NH;
                    int m0 = (uu & 7) * 32, n0 = (uu >> 3) * 64;
                    float acc[4][4] = {};
                    tile256<0, 32>(g_h2, g_W2, SM, H4, H4, m0, n0, 0, H4, acc);
                    int n = n0 + tx * 4;
                    float4 bb = *(const float4*)(g_b2 + n);
#pragma unroll
                    for (int r = 0; r < 2; r++) {
                        int m = m0 + ty * 2 + r;
                        float4 qv = *(const float4*)(Qt + (size_t)m * HH + n);
                        *(float4*)(od + (size_t)m * HH + n) = make_float4(
                            qv.x + acc[r][0] + bb.x, qv.y + acc[r][1] + bb.y,
                            qv.z + acc[r][2] + bb.z, qv.w + acc[r][3] + bb.w);
                    }
                } else {
                    // S1: part[sk] = Zt @ W1^T (k slice)
                    const int v = uu - 128;
                    const float* Zt = g_Z + (size_t)step * NH;
                    int sk = v & 7, tile = v >> 3;
                    int m0 = (tile & 3) * 64, n0 = (tile >> 2) * 64;
                    float acc[4][4] = {};
                    tile256<0, 64>(Zt, g_W1, SM, DD, DD, m0, n0,
                                   sk * 128, sk * 128 + 128, acc);
                    float* cp = g_part + (size_t)sk * MN;
#pragma unroll
                    for (int r = 0; r < 4; r++)
                        *(float4*)(cp + (size_t)(m0 + ty * 4 + r) * H4 + n0 + tx * 4) =
                            make_float4(acc[r][0], acc[r][1], acc[r][2], acc[r][3]);
                }
            }
        }
        grid_sync(nb);
        if (step == T_) break;

        const int t = step;
        const float* Zt = g_Z + (size_t)t * NH;
        const float* Yt = g_Y + (size_t)t * NH;
        const float* Qt = g_Q + (size_t)t * NH;

        // ---- R1: a = sum(part)+b1; h = gelu(a) ----
        for (int idx = bid * 256 + tid; idx < MN; idx += nb * 256) {
            float s = 0.f;
#pragma unroll
            for (int z = 0; z < 8; z++) s += g_part[(size_t)z * MN + idx];
            s += g_b1[idx & (H4 - 1)];
            g_a[idx] = s;
            g_h[idx] = gelu_f(s);
        }
        grid_sync(nb);

        // ---- R2: dr = C2*(Zt + h@W2^T + b2 - Yt) (128 u, 32x64 NT, OLD W2) ----
        for (int u = bid; u < 128; u += nb) {
            int m0 = (u & 7) * 32, n0 = (u >> 3) * 64;
            float acc[4][4] = {};
            tile256<0, 32>(g_h, g_W2, SM, H4, H4, m0, n0, 0, H4, acc);
            int n = n0 + tx * 4;
            float4 bb = *(const float4*)(g_b2 + n);
#pragma unroll
            for (int r = 0; r < 2; r++) {
                int m = m0 + ty * 2 + r;
                float4 zz = *(const float4*)(Zt + (size_t)m * HH + n);
                float4 yy = *(const float4*)(Yt + (size_t)m * HH + n);
                *(float4*)(g_dr + (size_t)m * HH + n) = make_float4(
                    C2 * (zz.x + acc[r][0] + bb.x - yy.x),
                    C2 * (zz.y + acc[r][1] + bb.y - yy.y),
                    C2 * (zz.z + acc[r][2] + bb.z - yy.z),
                    C2 * (zz.w + acc[r][3] + bb.w - yy.w));
            }
        }
        grid_sync(nb);

        // ---- R3: da_pre partials = dr @ W2 (NN, 128 u, 64x64, OLD W2) ----
        for (int u = bid; u < 128; u += nb) {
            int sk = u & 7, tile = u >> 3;
            int m0 = (tile & 3) * 64, n0 = (tile >> 2) * 64;
            float acc[4][4] = {};
            tile256<1, 64>(g_dr, g_W2, SM, HH, H4, m0, n0,
                           sk * 128, sk * 128 + 128, acc);
            float* cp = g_part + (size_t)sk * MN;
#pragma unroll
            for (int r = 0; r < 4; r++)
                *(float4*)(cp + (size_t)(m0 + ty * 4 + r) * H4 + n0 + tx * 4) =
                    make_float4(acc[r][0], acc[r][1], acc[r][2], acc[r][3]);
        }
        grid_sync(nb);

        // ---- R4: da = sum(part) * gelu'(a) ----
        for (int idx = bid * 256 + tid; idx < MN; idx += nb * 256) {
            float s = 0.f;
#pragma unroll
            for (int z = 0; z < 8; z++) s += g_part[(size_t)z * MN + idx];
            g_da[idx] = s * gelu_grad(g_a[idx]);
        }
        grid_sync(nb);

        // ---- R5: weight updates (128 TN units, 64x64, Kn=256) + biases ----
        for (int u = bid; u < 128; u += nb) {
            if (u < 64) {
                // W2[i,j] -= LR * sum_n dr[n,i] h[n,j]
                int i0 = (u & 15) * 64, j0 = (u >> 4) * 64;
                float acc[4][4] = {};
                tile256<2, 64>(g_dr, g_h, SM, HH, H4, i0, j0, 0, NB, acc);
#pragma unroll
                for (int r = 0; r < 4; r++) {
                    float* pp = g_W2 + (size_t)(i0 + ty * 4 + r) * H4 + j0 + tx * 4;
                    float4 o = *(float4*)pp;
                    o.x -= LR * acc[r][0]; o.y -= LR * acc[r][1];
                    o.z -= LR * acc[r][2]; o.w -= LR * acc[r][3];
                    *(float4*)pp = o;
                }
            } else {
                // W1[j,i] -= LR * sum_n da[n,j] Zt[n,i]
                int v = u - 64;
                int j0 = (v & 3) * 64, i0 = (v >> 2) * 64;
                float acc[4][4] = {};
                tile256<2, 64>(g_da, Zt, SM, H4, DD, j0, i0, 0, NB, acc);
#pragma unroll
                for (int r = 0; r < 4; r++) {
                    float* pp = g_W1 + (size_t)(j0 + ty * 4 + r) * DD + i0 + tx * 4;
                    float4 o = *(float4*)pp;
                    o.x -= LR * acc[r][0]; o.y -= LR * acc[r][1];
                    o.z -= LR * acc[r][2]; o.w -= LR * acc[r][3];
                    *(float4*)pp = o;
                }
            }
        }
        // bias colsums (warp-parallel, no intra-block syncs)
        for (int c = gw; c < HH; c += nb * 8) {
            float s = 0.f;
            for (int n = lane; n < NB; n += 32) s += g_dr[(size_t)n * HH + c];
#pragma unroll
            for (int o = 16; o > 0; o >>= 1) s += __shfl_xor_sync(0xffffffffu, s, o);
            if (lane == 0) g_b2[c] -= LR * s;
        }
        for (int c = gw; c < H4; c += nb * 8) {
            float s = 0.f;
            for (int n = lane; n < NB; n += 32) s += g_da[(size_t)n * H4 + c];
#pragma unroll
            for (int o = 16; o > 0; o >>= 1) s += __shfl_xor_sync(0xffffffffu, s, o);
            if (lane == 0) g_b1[c] -= LR * s;
        }
        grid_sync(nb);

        // ---- R6: a2 partials = Qt @ W1_new^T (128 u, 64x64 NT) ----
        for (int u = bid; u < 128; u += nb) {
            int sk = u & 7, tile = u >> 3;
            int m0 = (tile & 3) * 64, n0 = (tile >> 2) * 64;
            float acc[4][4] = {};
            tile256<0, 64>(Qt, g_W1, SM, DD, DD, m0, n0,
                           sk * 128, sk * 128 + 128, acc);
            float* cp = g_part + (size_t)sk * MN;
#pragma unroll
            for (int r = 0; r < 4; r++)
                *(float4*)(cp + (size_t)(m0 + ty * 4 + r) * H4 + n0 + tx * 4) =
                    make_float4(acc[r][0], acc[r][1], acc[r][2], acc[r][3]);
        }
        grid_sync(nb);

        // ---- R7: h2 = gelu(sum(part) + b1_new) ----
        for (int idx = bid * 256 + tid; idx < MN; idx += nb * 256) {
            float s = 0.f;
#pragma unroll
            for (int z = 0; z < 8; z++) s += g_part[(size_t)z * MN + idx];
            s += g_b1[idx & (H4 - 1)];
            g_h2[idx] = gelu_f(s);
        }
        grid_sync(nb);
    }
}

// ---------------------------------------------------------------------------
// kernel_launch
// ---------------------------------------------------------------------------
extern "C" void kernel_launch(void* const* d_in, const int* in_sizes, int n_in,
                              void* d_out, int out_size)
{
    (void)in_sizes; (void)n_in; (void)out_size;
    const float* in_seq = (const float*)d_in[0];
    const float* t_k = (const float*)d_in[1];
    const float* t_v = (const float*)d_in[2];
    const float* t_q = (const float*)d_in[3];

    float *Z, *Y, *Q, *W1, *b1, *W2, *b2;
    cudaGetSymbolAddress((void**)&Z, g_Z);
    cudaGetSymbolAddress((void**)&Y, g_Y);
    cudaGetSymbolAddress((void**)&Q, g_Q);
    cudaGetSymbolAddress((void**)&W1, g_W1);
    cudaGetSymbolAddress((void**)&b1, g_b1);
    cudaGetSymbolAddress((void**)&W2, g_W2);
    cudaGetSymbolAddress((void**)&b2, g_b2);

    cudaMemcpyAsync(W1, d_in[4], sizeof(float) * H4 * HH, cudaMemcpyDeviceToDevice, 0);
    cudaMemcpyAsync(b1, d_in[5], sizeof(float) * H4, cudaMemcpyDeviceToDevice, 0);
    cudaMemcpyAsync(W2, d_in[6], sizeof(float) * HH * H4, cudaMemcpyDeviceToDevice, 0);
    cudaMemcpyAsync(b2, d_in[7], sizeof(float) * HH, cudaMemcpyDeviceToDevice, 0);

    // Phase A: tf32 tensor-core GEMMs
    const int M_big = T_ * NB;
    dim3 gA(M_big / 128, HH / 128);
    gemm_nt_tf32<<<gA, 256>>>(in_seq, t_k, Z, M_big, HH, DD);
    gemm_nt_tf32<<<gA, 256>>>(in_seq, t_v, Y, M_big, HH, DD);
    gemm_nt_tf32<<<gA, 256>>>(in_seq, t_q, Q, M_big, HH, DD);

    // Phase B: one persistent kernel, exactly one block per SM.
    int sms = 0;
    cudaDeviceGetAttribute(&sms, cudaDevAttrMultiProcessorCount, 0);
    if (sms <= 0 || sms > 148) sms = 148;
    ttt_persistent<<<sms, 256>>>((float*)d_out, sms);
}

// round 10
// speedup vs baseline: 1.6719x; 1.1059x over previous
#include <cuda_runtime.h>
#include <cuda_bf16.h>
#include <cstdint>
#include <cstddef>

// ---------------------------------------------------------------------------
// TTLinear. Phase A: 3 big tf32 tensor-core GEMMs. Phase B: one persistent
// kernel (256 thr/block, 1 block/SM), 128 sequential SGD steps, 8 barriers.
// R10: gradient-path GEMMs (S1, R2, R3, R5) on tf32 mma.sync (tensor pipe);
// output-path GEMMs (R6, R0a) stay exact fp32 SIMT. Gradient tf32 error is
// damped by LR before it can reach the output.
// ---------------------------------------------------------------------------

constexpr int T_  = 128;
constexpr int NB  = 256;
constexpr int DD  = 1024;
constexpr int HH  = 1024;
constexpr int H4  = 256;
constexpr int NH  = NB * HH;    // 262144
constexpr int MN  = NB * H4;    // 65536
constexpr float LR = 1e-3f;
constexpr float C2 = 2.0f / (float)(NB * HH);

constexpr int SL   = 76;        // smem row stride: 76 mod 32 = 12 -> frag loads
                                // hit q*12+g = all-distinct banks; float4-aligned
constexpr int SLAB = 16 * SL;

// ------------------------- device scratch ----------------------------------
__device__ float g_Z[(size_t)T_ * NH];
__device__ float g_Y[(size_t)T_ * NH];
__device__ float g_Q[(size_t)T_ * NH];
__device__ float g_W1[H4 * HH];
__device__ float g_b1[H4];
__device__ float g_W2[HH * H4];
__device__ float g_b2[HH];
__device__ float g_a[MN];
__device__ float g_h[MN];
__device__ float g_h2[MN];
__device__ float g_da[MN];
__device__ float g_dr[NB * HH];
__device__ float g_part[8 * MN];

__device__ __align__(128) unsigned g_cnt = 0;
__device__ __align__(128) unsigned g_gen = 0;

// ------------------------------ helpers ------------------------------------
__device__ __forceinline__ float gelu_f(float x) {
    return 0.5f * x * (1.0f + erff(x * 0.70710678118654752f));
}
__device__ __forceinline__ float gelu_grad(float x) {
    float cdf = 0.5f * (1.0f + erff(x * 0.70710678118654752f));
    float pdf = 0.3989422804014327f * expf(-0.5f * x * x);
    return cdf + x * pdf;
}
__device__ __forceinline__ float to_tf32(float x) {
    uint32_t u;
    asm("cvt.rna.tf32.f32 %0, %1;" : "=r"(u) : "f"(x));
    return __uint_as_float(u);
}
__device__ __forceinline__ void mma_tf32(float (&c)[4], const uint32_t (&a)[4],
                                         const uint32_t (&b)[2]) {
    asm volatile(
        "mma.sync.aligned.m16n8k8.row.col.f32.tf32.tf32.f32 "
        "{%0,%1,%2,%3}, {%4,%5,%6,%7}, {%8,%9}, {%0,%1,%2,%3};"
        : "+f"(c[0]), "+f"(c[1]), "+f"(c[2]), "+f"(c[3])
        : "r"(a[0]), "r"(a[1]), "r"(a[2]), "r"(a[3]), "r"(b[0]), "r"(b[1]));
}

// Hot-spin grid barrier, bounded (sync bug -> wrong output, not a hang).
__device__ __forceinline__ void grid_sync(unsigned nb) {
    __syncthreads();
    if (threadIdx.x == 0) {
        unsigned gen = *(volatile unsigned*)&g_gen;
        __threadfence();
        if (atomicAdd(&g_cnt, 1) == nb - 1) {
            g_cnt = 0;
            __threadfence();
            atomicAdd(&g_gen, 1);
        } else {
            for (int spin = 0; spin < 1000000; spin++) {
                if (*(volatile unsigned*)&g_gen != gen) break;
            }
        }
        __threadfence();
    }
    __syncthreads();
}

// ---------------------------------------------------------------------------
// Phase A: C[M,N] = A[M,K] @ B[N,K]^T via tf32 mma.sync (unchanged).
// ---------------------------------------------------------------------------
__global__ __launch_bounds__(256, 2) void gemm_nt_tf32(
    const float* __restrict__ A, const float* __restrict__ B,
    float* __restrict__ C, int M, int N, int K)
{
    __shared__ float As[2][16][136];
    __shared__ float Bs[2][16][136];
    const int m0 = blockIdx.x * 128, n0 = blockIdx.y * 128;
    const int tid = threadIdx.x;
    const int lrow = tid & 127, lc8 = (tid >> 7) * 8;
    const int w = tid >> 5, lane = tid & 31;
    const int wm = w >> 2, wn = w & 3;
    const int g = lane >> 2, q = lane & 3;

    float acc[4][4][4] = {};
    const float* Ag = A + (size_t)(m0 + lrow) * K + lc8;
    const float* Bg = B + (size_t)(n0 + lrow) * K + lc8;

    float4 ra0 = *(const float4*)(Ag);
    float4 ra1 = *(const float4*)(Ag + 4);
    float4 rb0 = *(const float4*)(Bg);
    float4 rb1 = *(const float4*)(Bg + 4);

    const int S = K / 16;
    for (int s = 0; s < S; s++) {
        const int buf = s & 1;
        {
            float* pa = &As[buf][lc8][lrow];
            pa[0*136] = to_tf32(ra0.x); pa[1*136] = to_tf32(ra0.y);
            pa[2*136] = to_tf32(ra0.z); pa[3*136] = to_tf32(ra0.w);
            pa[4*136] = to_tf32(ra1.x); pa[5*136] = to_tf32(ra1.y);
            pa[6*136] = to_tf32(ra1.z); pa[7*136] = to_tf32(ra1.w);
            float* pb = &Bs[buf][lc8][lrow];
            pb[0*136] = to_tf32(rb0.x); pb[1*136] = to_tf32(rb0.y);
            pb[2*136] = to_tf32(rb0.z); pb[3*136] = to_tf32(rb0.w);
            pb[4*136] = to_tf32(rb1.x); pb[5*136] = to_tf32(rb1.y);
            pb[6*136] = to_tf32(rb1.z); pb[7*136] = to_tf32(rb1.w);
        }
        if (s + 1 < S) {
            const float* a2 = Ag + (s + 1) * 16;
            const float* b2 = Bg + (s + 1) * 16;
            ra0 = *(const float4*)(a2);     ra1 = *(const float4*)(a2 + 4);
            rb0 = *(const float4*)(b2);     rb1 = *(const float4*)(b2 + 4);
        }
        __syncthreads();
#pragma unroll
        for (int kc = 0; kc < 16; kc += 8) {
            uint32_t af[4][4], bf[4][2];
#pragma unroll
            for (int mt = 0; mt < 4; mt++) {
                int r = wm * 64 + mt * 16 + g;
                af[mt][0] = __float_as_uint(As[buf][kc + q][r]);
                af[mt][1] = __float_as_uint(As[buf][kc + q][r + 8]);
                af[mt][2] = __float_as_uint(As[buf][kc + q + 4][r]);
                af[mt][3] = __float_as_uint(As[buf][kc + q + 4][r + 8]);
            }
#pragma unroll
            for (int nt = 0; nt < 4; nt++) {
                int c = wn * 32 + nt * 8 + g;
                bf[nt][0] = __float_as_uint(Bs[buf][kc + q][c]);
                bf[nt][1] = __float_as_uint(Bs[buf][kc + q + 4][c]);
            }
#pragma unroll
            for (int mt = 0; mt < 4; mt++)
#pragma unroll
                for (int nt = 0; nt < 4; nt++)
                    mma_tf32(acc[mt][nt], af[mt], bf[nt]);
        }
        __syncthreads();
    }
#pragma unroll
    for (int mt = 0; mt < 4; mt++)
#pragma unroll
        for (int nt = 0; nt < 4; nt++) {
            int r = m0 + wm * 64 + mt * 16 + g;
            int c = n0 + wn * 32 + nt * 8 + q * 2;
            *(float2*)&C[(size_t)r * N + c] =
                make_float2(acc[mt][nt][0], acc[mt][nt][1]);
            *(float2*)&C[(size_t)(r + 8) * N + c] =
                make_float2(acc[mt][nt][2], acc[mt][nt][3]);
        }
}

// ---------------------------------------------------------------------------
// Shared staging for Phase B tiles: k-major smem As[k][m], Bs[k][n].
// MODE 0 NT: A[m,k],B[n,k]; MODE 1 NN: A[m,k],B[k,n]; MODE 2 TN: A[k,m],B[k,n]
// ---------------------------------------------------------------------------
template <int MODE, int TM>
struct Stage {
    float4 ra, rb; float2 ra2;
    __device__ __forceinline__ void fetch(const float* A, const float* B,
                                          int lda, int ldb, int m0, int n0, int k0,
                                          int tid) {
        if (MODE == 2) {
            ra = *(const float4*)(A + (size_t)(k0 + (tid >> 4)) * lda + m0 + (tid & 15) * 4);
        } else if (TM == 64) {
            ra = *(const float4*)(A + (size_t)(m0 + (tid >> 2)) * lda + k0 + (tid & 3) * 4);
        } else {
            ra2 = *(const float2*)(A + (size_t)(m0 + (tid >> 3)) * lda + k0 + (tid & 7) * 2);
        }
        if (MODE == 0) {
            rb = *(const float4*)(B + (size_t)(n0 + (tid >> 2)) * ldb + k0 + (tid & 3) * 4);
        } else {
            rb = *(const float4*)(B + (size_t)(k0 + (tid >> 4)) * ldb + n0 + (tid & 15) * 4);
        }
    }
    __device__ __forceinline__ void store(float* dA, float* dB, int tid) {
        if (MODE == 2) {
            *(float4*)(dA + (tid >> 4) * SL + (tid & 15) * 4) = ra;
        } else if (TM == 64) {
            int r = tid >> 2, c = (tid & 3) * 4;
            dA[(c + 0) * SL + r] = ra.x; dA[(c + 1) * SL + r] = ra.y;
            dA[(c + 2) * SL + r] = ra.z; dA[(c + 3) * SL + r] = ra.w;
        } else {
            int r = tid >> 3, c = (tid & 7) * 2;
            dA[(c + 0) * SL + r] = ra2.x; dA[(c + 1) * SL + r] = ra2.y;
        }
        if (MODE == 0) {
            int r = tid >> 2, c = (tid & 3) * 4;
            dB[(c + 0) * SL + r] = rb.x; dB[(c + 1) * SL + r] = rb.y;
            dB[(c + 2) * SL + r] = rb.z; dB[(c + 3) * SL + r] = rb.w;
        } else {
            *(float4*)(dB + (tid >> 4) * SL + (tid & 15) * 4) = rb;
        }
    }
};

// fp32 SIMT tile (exact; output path). TM=64: 4x4 micro; TM=32: 2x4 micro.
template <int MODE, int TM>
__device__ __forceinline__ void tile_f32(
    const float* __restrict__ A, const float* __restrict__ B, float* sm,
    int lda, int ldb, int m0, int n0, int kbeg, int kend,
    float (&acc)[4][4])
{
    const int tid = threadIdx.x;
    const int tx = tid & 15, ty = tid >> 4;
    float* smA = sm;
    float* smB = sm + 2 * SLAB;
    const int nslab = (kend - kbeg) >> 4;
    Stage<MODE, TM> st;

    st.fetch(A, B, lda, ldb, m0, n0, kbeg, tid);
    for (int s = 0; s < nslab; s++) {
        const int buf = s & 1;
        st.store(smA + buf * SLAB, smB + buf * SLAB, tid);
        if (s + 1 < nslab) st.fetch(A, B, lda, ldb, m0, n0, kbeg + (s + 1) * 16, tid);
        __syncthreads();
        const float* cA = smA + buf * SLAB;
        const float* cB = smB + buf * SLAB;
#pragma unroll
        for (int k = 0; k < 16; k++) {
            float4 b = *(const float4*)(cB + k * SL + tx * 4);
            if (TM == 64) {
                float4 a = *(const float4*)(cA + k * SL + ty * 4);
#pragma unroll
                for (int j = 0; j < 4; j++) {
                    float bj = (&b.x)[j];
                    acc[0][j] += a.x * bj; acc[1][j] += a.y * bj;
                    acc[2][j] += a.z * bj; acc[3][j] += a.w * bj;
                }
            } else {
                float2 a = *(const float2*)(cA + k * SL + ty * 2);
#pragma unroll
                for (int j = 0; j < 4; j++) {
                    float bj = (&b.x)[j];
                    acc[0][j] += a.x * bj; acc[1][j] += a.y * bj;
                }
            }
        }
        __syncthreads();
    }
}

// tf32 mma tile (gradient path). 8 warps = 2x4 grid, warp tile (TM/2)x16.
// acc[mt][nt][4] per m16n8k8 C layout. Inputs used as-is (truncation to tf32
// inside mma); gradient-path tolerance makes rna-rounding unnecessary.
template <int MODE, int TM>
__device__ __forceinline__ void tile_mma(
    const float* __restrict__ A, const float* __restrict__ B, float* sm,
    int lda, int ldb, int m0, int n0, int kbeg, int kend,
    float (&acc)[TM / 32][2][4])
{
    const int tid = threadIdx.x;
    const int w = tid >> 5, lane = tid & 31;
    const int wm = w >> 2, wn = w & 3;
    const int g = lane >> 2, q = lane & 3;
    float* smA = sm;
    float* smB = sm + 2 * SLAB;
    const int nslab = (kend - kbeg) >> 4;
    Stage<MODE, TM> st;

    st.fetch(A, B, lda, ldb, m0, n0, kbeg, tid);
    for (int s = 0; s < nslab; s++) {
        const int buf = s & 1;
        st.store(smA + buf * SLAB, smB + buf * SLAB, tid);
        if (s + 1 < nslab) st.fetch(A, B, lda, ldb, m0, n0, kbeg + (s + 1) * 16, tid);
        __syncthreads();
        const float* cA = smA + buf * SLAB;
        const float* cB = smB + buf * SLAB;
#pragma unroll
        for (int kc = 0; kc < 16; kc += 8) {
            uint32_t af[TM / 32][4], bf[2][2];
#pragma unroll
            for (int mt = 0; mt < TM / 32; mt++) {
                int r = wm * (TM / 2) + mt * 16 + g;
                af[mt][0] = __float_as_uint(cA[(kc + q) * SL + r]);
                af[mt][1] = __float_as_uint(cA[(kc + q) * SL + r + 8]);
                af[mt][2] = __float_as_uint(cA[(kc + q + 4) * SL + r]);
                af[mt][3] = __float_as_uint(cA[(kc + q + 4) * SL + r + 8]);
            }
#pragma unroll
            for (int nt = 0; nt < 2; nt++) {
                int c = wn * 16 + nt * 8 + g;
                bf[nt][0] = __float_as_uint(cB[(kc + q) * SL + c]);
                bf[nt][1] = __float_as_uint(cB[(kc + q + 4) * SL + c]);
            }
#pragma unroll
            for (int mt = 0; mt < TM / 32; mt++)
#pragma unroll
                for (int nt = 0; nt < 2; nt++)
                    mma_tf32(acc[mt][nt], af[mt], bf[nt]);
        }
        __syncthreads();
    }
}

// ---------------------------------------------------------------------------
// Persistent Phase B kernel: 256 threads/block, one tile-unit per block/wave.
// ---------------------------------------------------------------------------
__global__ __launch_bounds__(256, 1) void ttt_persistent(float* __restrict__ out,
                                                         int nb)
{
    __shared__ __align__(16) float SM[4 * SLAB];
    const int bid = blockIdx.x, tid = threadIdx.x;
    const int tx = tid & 15, ty = tid >> 4;
    const int w = tid >> 5, lane = tid & 31;
    const int wm = w >> 2, wn = w & 3;
    const int g = lane >> 2, q = lane & 3;
    const int gw = (bid * 256 + tid) >> 5;

    for (int step = 0; step <= T_; step++) {
        // ---- R0: S10 of step-1 (fp32, 128 u, 32x64, K=256)
        //        + S1 partials of step (tf32 mma, 128 u, 64x64, K=128) ----
        {
            const int nA = (step > 0) ? 128 : 0;
            const int nTot = nA + ((step < T_) ? 128 : 0);
            for (int u = bid; u < nTot; u += nb) {
                const int uu = (step > 0) ? u : u + 128;
                if (uu < 128) {
                    // S10: out[t-1] = Qt + h2 @ W2^T + b2 (EXACT fp32)
                    const int t = step - 1;
                    const float* Qt = g_Q + (size_t)t * NH;
                    float* od = out + (size_t)t * NH;
                    int m0 = (uu & 7) * 32, n0 = (uu >> 3) * 64;
                    float acc[4][4] = {};
                    tile_f32<0, 32>(g_h2, g_W2, SM, H4, H4, m0, n0, 0, H4, acc);
                    int n = n0 + tx * 4;
                    float4 bb = *(const float4*)(g_b2 + n);
#pragma unroll
                    for (int r = 0; r < 2; r++) {
                        int m = m0 + ty * 2 + r;
                        float4 qv = *(const float4*)(Qt + (size_t)m * HH + n);
                        *(float4*)(od + (size_t)m * HH + n) = make_float4(
                            qv.x + acc[r][0] + bb.x, qv.y + acc[r][1] + bb.y,
                            qv.z + acc[r][2] + bb.z, qv.w + acc[r][3] + bb.w);
                    }
                } else {
                    // S1: part[sk] = Zt @ W1^T slice (tf32 mma)
                    const int v = uu - 128;
                    const float* Zt = g_Z + (size_t)step * NH;
                    int sk = v & 7, tile = v >> 3;
                    int m0 = (tile & 3) * 64, n0 = (tile >> 2) * 64;
                    float acc[2][2][4] = {};
                    tile_mma<0, 64>(Zt, g_W1, SM, DD, DD, m0, n0,
                                    sk * 128, sk * 128 + 128, acc);
                    float* cp = g_part + (size_t)sk * MN;
#pragma unroll
                    for (int mt = 0; mt < 2; mt++)
#pragma unroll
                        for (int nt = 0; nt < 2; nt++) {
                            int m = m0 + wm * 32 + mt * 16 + g;
                            int nn = n0 + wn * 16 + nt * 8 + q * 2;
                            *(float2*)(cp + (size_t)m * H4 + nn) =
                                make_float2(acc[mt][nt][0], acc[mt][nt][1]);
                            *(float2*)(cp + (size_t)(m + 8) * H4 + nn) =
                                make_float2(acc[mt][nt][2], acc[mt][nt][3]);
                        }
                }
            }
        }
        grid_sync(nb);
        if (step == T_) break;

        const int t = step;
        const float* Zt = g_Z + (size_t)t * NH;
        const float* Yt = g_Y + (size_t)t * NH;
        const float* Qt = g_Q + (size_t)t * NH;

        // ---- R1: a = sum(part)+b1; h = gelu(a) ----
        for (int idx = bid * 256 + tid; idx < MN; idx += nb * 256) {
            float s = 0.f;
#pragma unroll
            for (int z = 0; z < 8; z++) s += g_part[(size_t)z * MN + idx];
            s += g_b1[idx & (H4 - 1)];
            g_a[idx] = s;
            g_h[idx] = gelu_f(s);
        }
        grid_sync(nb);

        // ---- R2: dr = C2*(Zt + h@W2^T + b2 - Yt) (tf32 mma, 128 u, 32x64) ----
        for (int u = bid; u < 128; u += nb) {
            int m0 = (u & 7) * 32, n0 = (u >> 3) * 64;
            float acc[1][2][4] = {};
            tile_mma<0, 32>(g_h, g_W2, SM, H4, H4, m0, n0, 0, H4, acc);
#pragma unroll
            for (int nt = 0; nt < 2; nt++) {
                int m = m0 + wm * 16 + g;
                int nn = n0 + wn * 16 + nt * 8 + q * 2;
                float2 bb = *(const float2*)(g_b2 + nn);
                {
                    float2 zz = *(const float2*)(Zt + (size_t)m * HH + nn);
                    float2 yy = *(const float2*)(Yt + (size_t)m * HH + nn);
                    *(float2*)(g_dr + (size_t)m * HH + nn) = make_float2(
                        C2 * (zz.x + acc[0][nt][0] + bb.x - yy.x),
                        C2 * (zz.y + acc[0][nt][1] + bb.y - yy.y));
                }
                {
                    int m8 = m + 8;
                    float2 zz = *(const float2*)(Zt + (size_t)m8 * HH + nn);
                    float2 yy = *(const float2*)(Yt + (size_t)m8 * HH + nn);
                    *(float2*)(g_dr + (size_t)m8 * HH + nn) = make_float2(
                        C2 * (zz.x + acc[0][nt][2] + bb.x - yy.x),
                        C2 * (zz.y + acc[0][nt][3] + bb.y - yy.y));
                }
            }
        }
        grid_sync(nb);

        // ---- R3: da_pre partials = dr @ W2 (tf32 mma NN, 128 u, 64x64) ----
        for (int u = bid; u < 128; u += nb) {
            int sk = u & 7, tile = u >> 3;
            int m0 = (tile & 3) * 64, n0 = (tile >> 2) * 64;
            float acc[2][2][4] = {};
            tile_mma<1, 64>(g_dr, g_W2, SM, HH, H4, m0, n0,
                            sk * 128, sk * 128 + 128, acc);
            float* cp = g_part + (size_t)sk * MN;
#pragma unroll
            for (int mt = 0; mt < 2; mt++)
#pragma unroll
                for (int nt = 0; nt < 2; nt++) {
                    int m = m0 + wm * 32 + mt * 16 + g;
                    int nn = n0 + wn * 16 + nt * 8 + q * 2;
                    *(float2*)(cp + (size_t)m * H4 + nn) =
                        make_float2(acc[mt][nt][0], acc[mt][nt][1]);
                    *(float2*)(cp + (size_t)(m + 8) * H4 + nn) =
                        make_float2(acc[mt][nt][2], acc[mt][nt][3]);
                }
        }
        grid_sync(nb);

        // ---- R4: da = sum(part) * gelu'(a) ----
        for (int idx = bid * 256 + tid; idx < MN; idx += nb * 256) {
            float s = 0.f;
#pragma unroll
            for (int z = 0; z < 8; z++) s += g_part[(size_t)z * MN + idx];
            g_da[idx] = s * gelu_grad(g_a[idx]);
        }
        grid_sync(nb);

        // ---- R5: weight updates (tf32 mma TN, 128 u, Kn=256) + biases ----
        for (int u = bid; u < 128; u += nb) {
            if (u < 64) {
                // W2[i,j] -= LR * sum_n dr[n,i] h[n,j]
                int i0 = (u & 15) * 64, j0 = (u >> 4) * 64;
                float acc[2][2][4] = {};
                tile_mma<2, 64>(g_dr, g_h, SM, HH, H4, i0, j0, 0, NB, acc);
#pragma unroll
                for (int mt = 0; mt < 2; mt++)
#pragma unroll
                    for (int nt = 0; nt < 2; nt++) {
                        int i = i0 + wm * 32 + mt * 16 + g;
                        int j = j0 + wn * 16 + nt * 8 + q * 2;
                        float2* p0 = (float2*)(g_W2 + (size_t)i * H4 + j);
                        float2 o0 = *p0;
                        o0.x -= LR * acc[mt][nt][0]; o0.y -= LR * acc[mt][nt][1];
                        *p0 = o0;
                        float2* p1 = (float2*)(g_W2 + (size_t)(i + 8) * H4 + j);
                        float2 o1 = *p1;
                        o1.x -= LR * acc[mt][nt][2]; o1.y -= LR * acc[mt][nt][3];
                        *p1 = o1;
                    }
            } else {
                // W1[j,i] -= LR * sum_n da[n,j] Zt[n,i]
                int v = u - 64;
                int j0 = (v & 3) * 64, i0 = (v >> 2) * 64;
                float acc[2][2][4] = {};
                tile_mma<2, 64>(g_da, Zt, SM, H4, DD, j0, i0, 0, NB, acc);
#pragma unroll
                for (int mt = 0; mt < 2; mt++)
#pragma unroll
                    for (int nt = 0; nt < 2; nt++) {
                        int j = j0 + wm * 32 + mt * 16 + g;
                        int i = i0 + wn * 16 + nt * 8 + q * 2;
                        float2* p0 = (float2*)(g_W1 + (size_t)j * DD + i);
                        float2 o0 = *p0;
                        o0.x -= LR * acc[mt][nt][0]; o0.y -= LR * acc[mt][nt][1];
                        *p0 = o0;
                        float2* p1 = (float2*)(g_W1 + (size_t)(j + 8) * DD + i);
                        float2 o1 = *p1;
                        o1.x -= LR * acc[mt][nt][2]; o1.y -= LR * acc[mt][nt][3];
                        *p1 = o1;
                    }
            }
        }
        // bias colsums (warp-parallel, no intra-block syncs)
        for (int c = gw; c < HH; c += nb * 8) {
            float s = 0.f;
            for (int n = lane; n < NB; n += 32) s += g_dr[(size_t)n * HH + c];
#pragma unroll
            for (int o = 16; o > 0; o >>= 1) s += __shfl_xor_sync(0xffffffffu, s, o);
            if (lane == 0) g_b2[c] -= LR * s;
        }
        for (int c = gw; c < H4; c += nb * 8) {
            float s = 0.f;
            for (int n = lane; n < NB; n += 32) s += g_da[(size_t)n * H4 + c];
#pragma unroll
            for (int o = 16; o > 0; o >>= 1) s += __shfl_xor_sync(0xffffffffu, s, o);
            if (lane == 0) g_b1[c] -= LR * s;
        }
        grid_sync(nb);

        // ---- R6: a2 partials = Qt @ W1_new^T (EXACT fp32, 128 u, 64x64) ----
        for (int u = bid; u < 128; u += nb) {
            int sk = u & 7, tile = u >> 3;
            int m0 = (tile & 3) * 64, n0 = (tile >> 2) * 64;
            float acc[4][4] = {};
            tile_f32<0, 64>(Qt, g_W1, SM, DD, DD, m0, n0,
                            sk * 128, sk * 128 + 128, acc);
            float* cp = g_part + (size_t)sk * MN;
#pragma unroll
            for (int r = 0; r < 4; r++)
                *(float4*)(cp + (size_t)(m0 + ty * 4 + r) * H4 + n0 + tx * 4) =
                    make_float4(acc[r][0], acc[r][1], acc[r][2], acc[r][3]);
        }
        grid_sync(nb);

        // ---- R7: h2 = gelu(sum(part) + b1_new) ----
        for (int idx = bid * 256 + tid; idx < MN; idx += nb * 256) {
            float s = 0.f;
#pragma unroll
            for (int z = 0; z < 8; z++) s += g_part[(size_t)z * MN + idx];
            s += g_b1[idx & (H4 - 1)];
            g_h2[idx] = gelu_f(s);
        }
        grid_sync(nb);
    }
}

// ---------------------------------------------------------------------------
// kernel_launch
// ---------------------------------------------------------------------------
extern "C" void kernel_launch(void* const* d_in, const int* in_sizes, int n_in,
                              void* d_out, int out_size)
{
    (void)in_sizes; (void)n_in; (void)out_size;
    const float* in_seq = (const float*)d_in[0];
    const float* t_k = (const float*)d_in[1];
    const float* t_v = (const float*)d_in[2];
    const float* t_q = (const float*)d_in[3];

    float *Z, *Y, *Q, *W1, *b1, *W2, *b2;
    cudaGetSymbolAddress((void**)&Z, g_Z);
    cudaGetSymbolAddress((void**)&Y, g_Y);
    cudaGetSymbolAddress((void**)&Q, g_Q);
    cudaGetSymbolAddress((void**)&W1, g_W1);
    cudaGetSymbolAddress((void**)&b1, g_b1);
    cudaGetSymbolAddress((void**)&W2, g_W2);
    cudaGetSymbolAddress((void**)&b2, g_b2);

    cudaMemcpyAsync(W1, d_in[4], sizeof(float) * H4 * HH, cudaMemcpyDeviceToDevice, 0);
    cudaMemcpyAsync(b1, d_in[5], sizeof(float) * H4, cudaMemcpyDeviceToDevice, 0);
    cudaMemcpyAsync(W2, d_in[6], sizeof(float) * HH * H4, cudaMemcpyDeviceToDevice, 0);
    cudaMemcpyAsync(b2, d_in[7], sizeof(float) * HH, cudaMemcpyDeviceToDevice, 0);

    // Phase A: tf32 tensor-core GEMMs
    const int M_big = T_ * NB;
    dim3 gA(M_big / 128, HH / 128);
    gemm_nt_tf32<<<gA, 256>>>(in_seq, t_k, Z, M_big, HH, DD);
    gemm_nt_tf32<<<gA, 256>>>(in_seq, t_v, Y, M_big, HH, DD);
    gemm_nt_tf32<<<gA, 256>>>(in_seq, t_q, Q, M_big, HH, DD);

    // Phase B: one persistent kernel, exactly one block per SM.
    int sms = 0;
    cudaDeviceGetAttribute(&sms, cudaDevAttrMultiProcessorCount, 0);
    if (sms <= 0 || sms > 148) sms = 148;
    ttt_persistent<<<sms, 256>>>((float*)d_out, sms);
}